// round 1
// baseline (speedup 1.0000x reference)
#include <cuda_runtime.h>
#include <math.h>

// Problem constants (B=2, N=1024 -> T=2048 tokens; D=768; E=8; H=3072; K=2)
#define T_TOK 2048
#define D_DIM 768
#define E_EXP 8
#define H_DIM 3072

// ---------------------------------------------------------------------------
// Static device scratch (allocation-free per harness rules)
// ---------------------------------------------------------------------------
__device__ int   g_count[E_EXP];                 // tokens per expert
__device__ int   g_tok[E_EXP * T_TOK];           // expert slot -> token id
__device__ int   g_np[T_TOK];                    // pairs per token
__device__ int   g_te[T_TOK * E_EXP];            // token -> expert list
__device__ int   g_ts[T_TOK * E_EXP];            // token -> slot-in-expert list
__device__ float g_h[(size_t)E_EXP * T_TOK * H_DIM];   // gelu(gate)*value, 201 MB
__device__ float g_y[(size_t)E_EXP * T_TOK * D_DIM];   // per-pair expert output, 50 MB

// ---------------------------------------------------------------------------
// Kernel 0: zero per-expert counters
// ---------------------------------------------------------------------------
__global__ void zero_counts_kernel() {
    int i = threadIdx.x;
    if (i < E_EXP) g_count[i] = 0;
}

// ---------------------------------------------------------------------------
// Kernel 1: build per-expert token lists + per-token (expert, slot) map
// ---------------------------------------------------------------------------
__global__ void build_kernel(const float* __restrict__ disp) {
    int t = blockIdx.x * blockDim.x + threadIdx.x;
    if (t >= T_TOK) return;
    int np = 0;
#pragma unroll
    for (int e = 0; e < E_EXP; e++) {
        if (disp[t * E_EXP + e] > 0.0f) {
            int s = atomicAdd(&g_count[e], 1);
            g_tok[e * T_TOK + s] = t;
            g_te[t * E_EXP + np] = e;
            g_ts[t * E_EXP + np] = s;
            np++;
        }
    }
    g_np[t] = np;
}

// ---------------------------------------------------------------------------
// Kernel 2: grouped GEMM1 (gate & value) + fused exact GELU * value -> g_h
//   For expert e: X_gathered[cnt x D] @ Wg[e]^T and @ Wv[e]^T  (Wg/Wv: (H,D))
//   Tile: 64 tokens x 64 H-cols, K-chunks of 16 over D. 256 thr, 4x4 microtile.
// ---------------------------------------------------------------------------
__global__ __launch_bounds__(256) void gemm1_kernel(
    const float* __restrict__ x,
    const float* __restrict__ Wg,
    const float* __restrict__ Wv)
{
    const int e   = blockIdx.z;
    const int cnt = g_count[e];
    const int m0  = blockIdx.x * 64;
    if (m0 >= cnt) return;
    const int n0  = blockIdx.y * 64;

    __shared__ float Xs[16][68];
    __shared__ float Gs[16][68];
    __shared__ float Vs[16][68];

    const int tid = threadIdx.x;
    const int mi  = tid & 15;   // token micro-col group (x4)
    const int ni  = tid >> 4;   // H micro-col group (x4)

    float accg[4][4] = {};
    float accv[4][4] = {};

    // Precompute gathered token ids for this thread's load duties
    int tks[4];
#pragma unroll
    for (int i = 0; i < 4; i++) {
        int m = (tid + i * 256) >> 4;
        tks[i] = (m0 + m < cnt) ? g_tok[e * T_TOK + m0 + m] : -1;
    }

    const float* wg = Wg + (size_t)e * H_DIM * D_DIM;
    const float* wv = Wv + (size_t)e * H_DIM * D_DIM;

    for (int k0 = 0; k0 < D_DIM; k0 += 16) {
        __syncthreads();
#pragma unroll
        for (int i = 0; i < 4; i++) {
            int idx = tid + i * 256;
            int r   = idx >> 4;      // 0..63 (token row / H row)
            int kk  = idx & 15;
            Xs[kk][r] = (tks[i] >= 0) ? x[(size_t)tks[i] * D_DIM + k0 + kk] : 0.0f;
            Gs[kk][r] = wg[(size_t)(n0 + r) * D_DIM + k0 + kk];
            Vs[kk][r] = wv[(size_t)(n0 + r) * D_DIM + k0 + kk];
        }
        __syncthreads();
#pragma unroll
        for (int kk = 0; kk < 16; kk++) {
            float4 a  = *(const float4*)&Xs[kk][mi * 4];
            float4 bg = *(const float4*)&Gs[kk][ni * 4];
            float4 bv = *(const float4*)&Vs[kk][ni * 4];
            float av[4]  = {a.x,  a.y,  a.z,  a.w};
            float bgv[4] = {bg.x, bg.y, bg.z, bg.w};
            float bvv[4] = {bv.x, bv.y, bv.z, bv.w};
#pragma unroll
            for (int i = 0; i < 4; i++) {
#pragma unroll
                for (int j = 0; j < 4; j++) {
                    accg[i][j] = fmaf(av[i], bgv[j], accg[i][j]);
                    accv[i][j] = fmaf(av[i], bvv[j], accv[i][j]);
                }
            }
        }
    }

    // Epilogue: exact GELU(gate) * value -> g_h
#pragma unroll
    for (int i = 0; i < 4; i++) {
        int slot = m0 + mi * 4 + i;
        if (slot < cnt) {
            float out[4];
#pragma unroll
            for (int j = 0; j < 4; j++) {
                float g  = accg[i][j];
                float gl = 0.5f * g * (1.0f + erff(g * 0.70710678118654752f));
                out[j]   = gl * accv[i][j];
            }
            float* hp = &g_h[((size_t)e * T_TOK + slot) * H_DIM + n0 + ni * 4];
            *(float4*)hp = make_float4(out[0], out[1], out[2], out[3]);
        }
    }
}

// ---------------------------------------------------------------------------
// Kernel 3: grouped GEMM2: ypart[cnt x D] = scale_e * (h[cnt x H] @ Wo[e]^T)
//   Wo: (D, H) row-major. Tile 64 slots x 64 D-cols, K-chunks of 16 over H.
// ---------------------------------------------------------------------------
__global__ __launch_bounds__(256) void gemm2_kernel(
    const float* __restrict__ Wo,
    const float* __restrict__ scale)
{
    const int e   = blockIdx.z;
    const int cnt = g_count[e];
    const int m0  = blockIdx.x * 64;
    if (m0 >= cnt) return;
    const int n0  = blockIdx.y * 64;

    __shared__ float Hs[16][68];
    __shared__ float Bs[16][68];

    const int tid = threadIdx.x;
    const int mi  = tid & 15;
    const int ni  = tid >> 4;

    float acc[4][4] = {};

    const float* wo = Wo + (size_t)e * D_DIM * H_DIM;
    const float* hb = &g_h[(size_t)e * T_TOK * H_DIM];

    bool mval[4];
    int  mrow[4];
#pragma unroll
    for (int i = 0; i < 4; i++) {
        int r   = (tid + i * 256) >> 4;
        mrow[i] = m0 + r;
        mval[i] = (m0 + r) < cnt;
    }

    for (int k0 = 0; k0 < H_DIM; k0 += 16) {
        __syncthreads();
#pragma unroll
        for (int i = 0; i < 4; i++) {
            int idx = tid + i * 256;
            int r   = idx >> 4;
            int kk  = idx & 15;
            Hs[kk][r] = mval[i] ? hb[(size_t)mrow[i] * H_DIM + k0 + kk] : 0.0f;
            Bs[kk][r] = wo[(size_t)(n0 + r) * H_DIM + k0 + kk];
        }
        __syncthreads();
#pragma unroll
        for (int kk = 0; kk < 16; kk++) {
            float4 a = *(const float4*)&Hs[kk][mi * 4];
            float4 b = *(const float4*)&Bs[kk][ni * 4];
            float av[4] = {a.x, a.y, a.z, a.w};
            float bv[4] = {b.x, b.y, b.z, b.w};
#pragma unroll
            for (int i = 0; i < 4; i++) {
#pragma unroll
                for (int j = 0; j < 4; j++) {
                    acc[i][j] = fmaf(av[i], bv[j], acc[i][j]);
                }
            }
        }
    }

    const float sc = scale[e];
#pragma unroll
    for (int i = 0; i < 4; i++) {
        int slot = m0 + mi * 4 + i;
        if (slot < cnt) {
            float* yp = &g_y[((size_t)e * T_TOK + slot) * D_DIM + n0 + ni * 4];
            *(float4*)yp = make_float4(acc[i][0] * sc, acc[i][1] * sc,
                                       acc[i][2] * sc, acc[i][3] * sc);
        }
    }
}

// ---------------------------------------------------------------------------
// Kernel 4: weighted combine -> d_out (single deterministic write per element)
// ---------------------------------------------------------------------------
__global__ void combine_kernel(const float* __restrict__ comb,
                               float* __restrict__ out)
{
    int idx = blockIdx.x * blockDim.x + threadIdx.x;
    if (idx >= T_TOK * D_DIM) return;
    int t = idx / D_DIM;
    int d = idx - t * D_DIM;
    float y  = 0.0f;
    int   np = g_np[t];
    for (int j = 0; j < np; j++) {
        int e = g_te[t * E_EXP + j];
        int s = g_ts[t * E_EXP + j];
        y += comb[t * E_EXP + e] * g_y[((size_t)e * T_TOK + s) * D_DIM + d];
    }
    out[idx] = y;
}

// ---------------------------------------------------------------------------
// Launch (graph-capturable: kernel launches only, default stream)
// Inputs (metadata order): tokens, dispatch_weights, combine_weights,
//                          Wg, Wv, Wo, scale
// ---------------------------------------------------------------------------
extern "C" void kernel_launch(void* const* d_in, const int* in_sizes, int n_in,
                              void* d_out, int out_size)
{
    const float* tokens = (const float*)d_in[0];
    const float* disp   = (const float*)d_in[1];
    const float* comb   = (const float*)d_in[2];
    const float* Wg     = (const float*)d_in[3];
    const float* Wv     = (const float*)d_in[4];
    const float* Wo     = (const float*)d_in[5];
    const float* scale  = (const float*)d_in[6];
    float* out = (float*)d_out;

    zero_counts_kernel<<<1, 32>>>();
    build_kernel<<<(T_TOK + 255) / 256, 256>>>(disp);

    dim3 g1(T_TOK / 64, H_DIM / 64, E_EXP);   // (32, 48, 8) — inactive tiles exit
    gemm1_kernel<<<g1, 256>>>(tokens, Wg, Wv);

    dim3 g2(T_TOK / 64, D_DIM / 64, E_EXP);   // (32, 12, 8)
    gemm2_kernel<<<g2, 256>>>(Wo, scale);

    combine_kernel<<<(T_TOK * D_DIM + 255) / 256, 256>>>(comb, out);
}

// round 2
// speedup vs baseline: 1.0007x; 1.0007x over previous
#include <cuda_runtime.h>
#include <math.h>

// Problem constants (B=2, N=1024 -> T=2048 tokens; D=768; E=8; H=3072; K=2)
#define T_TOK 2048
#define D_DIM 768
#define E_EXP 8
#define H_DIM 3072

// ---------------------------------------------------------------------------
// Static device scratch (allocation-free per harness rules)
// ---------------------------------------------------------------------------
__device__ int   g_count[E_EXP];                 // tokens per expert
__device__ int   g_tok[E_EXP * T_TOK];           // expert slot -> token id
__device__ int   g_np[T_TOK];                    // pairs per token
__device__ int   g_te[T_TOK * E_EXP];            // token -> expert list
__device__ int   g_ts[T_TOK * E_EXP];            // token -> slot-in-expert list
__device__ float g_h[(size_t)E_EXP * T_TOK * H_DIM];   // gelu(gate)*value, 201 MB
__device__ float g_y[(size_t)E_EXP * T_TOK * D_DIM];   // per-pair expert output, 50 MB

// ---------------------------------------------------------------------------
// Kernel 0: zero per-expert counters
// ---------------------------------------------------------------------------
__global__ void zero_counts_kernel() {
    int i = threadIdx.x;
    if (i < E_EXP) g_count[i] = 0;
}

// ---------------------------------------------------------------------------
// Kernel 1: build per-expert token lists + per-token (expert, slot) map
// ---------------------------------------------------------------------------
__global__ void build_kernel(const float* __restrict__ disp) {
    int t = blockIdx.x * blockDim.x + threadIdx.x;
    if (t >= T_TOK) return;
    int np = 0;
#pragma unroll
    for (int e = 0; e < E_EXP; e++) {
        if (disp[t * E_EXP + e] > 0.0f) {
            int s = atomicAdd(&g_count[e], 1);
            g_tok[e * T_TOK + s] = t;
            g_te[t * E_EXP + np] = e;
            g_ts[t * E_EXP + np] = s;
            np++;
        }
    }
    g_np[t] = np;
}

// ---------------------------------------------------------------------------
// Kernel 2: grouped GEMM1 (gate & value) + fused exact GELU * value -> g_h
//   For expert e: X_gathered[cnt x D] @ Wg[e]^T and @ Wv[e]^T  (Wg/Wv: (H,D))
//   Tile: 64 tokens x 64 H-cols, K-chunks of 16 over D. 256 thr, 4x4 microtile.
// ---------------------------------------------------------------------------
__global__ __launch_bounds__(256) void gemm1_kernel(
    const float* __restrict__ x,
    const float* __restrict__ Wg,
    const float* __restrict__ Wv)
{
    const int e   = blockIdx.z;
    const int cnt = g_count[e];
    const int m0  = blockIdx.x * 64;
    if (m0 >= cnt) return;
    const int n0  = blockIdx.y * 64;

    __shared__ float Xs[16][68];
    __shared__ float Gs[16][68];
    __shared__ float Vs[16][68];

    const int tid = threadIdx.x;
    const int mi  = tid & 15;   // token micro-col group (x4)
    const int ni  = tid >> 4;   // H micro-col group (x4)

    float accg[4][4] = {};
    float accv[4][4] = {};

    // Precompute gathered token ids for this thread's load duties
    int tks[4];
#pragma unroll
    for (int i = 0; i < 4; i++) {
        int m = (tid + i * 256) >> 4;
        tks[i] = (m0 + m < cnt) ? g_tok[e * T_TOK + m0 + m] : -1;
    }

    const float* wg = Wg + (size_t)e * H_DIM * D_DIM;
    const float* wv = Wv + (size_t)e * H_DIM * D_DIM;

    for (int k0 = 0; k0 < D_DIM; k0 += 16) {
        __syncthreads();
#pragma unroll
        for (int i = 0; i < 4; i++) {
            int idx = tid + i * 256;
            int r   = idx >> 4;      // 0..63 (token row / H row)
            int kk  = idx & 15;
            Xs[kk][r] = (tks[i] >= 0) ? x[(size_t)tks[i] * D_DIM + k0 + kk] : 0.0f;
            Gs[kk][r] = wg[(size_t)(n0 + r) * D_DIM + k0 + kk];
            Vs[kk][r] = wv[(size_t)(n0 + r) * D_DIM + k0 + kk];
        }
        __syncthreads();
#pragma unroll
        for (int kk = 0; kk < 16; kk++) {
            float4 a  = *(const float4*)&Xs[kk][mi * 4];
            float4 bg = *(const float4*)&Gs[kk][ni * 4];
            float4 bv = *(const float4*)&Vs[kk][ni * 4];
            float av[4]  = {a.x,  a.y,  a.z,  a.w};
            float bgv[4] = {bg.x, bg.y, bg.z, bg.w};
            float bvv[4] = {bv.x, bv.y, bv.z, bv.w};
#pragma unroll
            for (int i = 0; i < 4; i++) {
#pragma unroll
                for (int j = 0; j < 4; j++) {
                    accg[i][j] = fmaf(av[i], bgv[j], accg[i][j]);
                    accv[i][j] = fmaf(av[i], bvv[j], accv[i][j]);
                }
            }
        }
    }

    // Epilogue: exact GELU(gate) * value -> g_h
#pragma unroll
    for (int i = 0; i < 4; i++) {
        int slot = m0 + mi * 4 + i;
        if (slot < cnt) {
            float out[4];
#pragma unroll
            for (int j = 0; j < 4; j++) {
                float g  = accg[i][j];
                float gl = 0.5f * g * (1.0f + erff(g * 0.70710678118654752f));
                out[j]   = gl * accv[i][j];
            }
            float* hp = &g_h[((size_t)e * T_TOK + slot) * H_DIM + n0 + ni * 4];
            *(float4*)hp = make_float4(out[0], out[1], out[2], out[3]);
        }
    }
}

// ---------------------------------------------------------------------------
// Kernel 3: grouped GEMM2: ypart[cnt x D] = scale_e * (h[cnt x H] @ Wo[e]^T)
//   Wo: (D, H) row-major. Tile 64 slots x 64 D-cols, K-chunks of 16 over H.
// ---------------------------------------------------------------------------
__global__ __launch_bounds__(256) void gemm2_kernel(
    const float* __restrict__ Wo,
    const float* __restrict__ scale)
{
    const int e   = blockIdx.z;
    const int cnt = g_count[e];
    const int m0  = blockIdx.x * 64;
    if (m0 >= cnt) return;
    const int n0  = blockIdx.y * 64;

    __shared__ float Hs[16][68];
    __shared__ float Bs[16][68];

    const int tid = threadIdx.x;
    const int mi  = tid & 15;
    const int ni  = tid >> 4;

    float acc[4][4] = {};

    const float* wo = Wo + (size_t)e * D_DIM * H_DIM;
    const float* hb = &g_h[(size_t)e * T_TOK * H_DIM];

    bool mval[4];
    int  mrow[4];
#pragma unroll
    for (int i = 0; i < 4; i++) {
        int r   = (tid + i * 256) >> 4;
        mrow[i] = m0 + r;
        mval[i] = (m0 + r) < cnt;
    }

    for (int k0 = 0; k0 < H_DIM; k0 += 16) {
        __syncthreads();
#pragma unroll
        for (int i = 0; i < 4; i++) {
            int idx = tid + i * 256;
            int r   = idx >> 4;
            int kk  = idx & 15;
            Hs[kk][r] = mval[i] ? hb[(size_t)mrow[i] * H_DIM + k0 + kk] : 0.0f;
            Bs[kk][r] = wo[(size_t)(n0 + r) * H_DIM + k0 + kk];
        }
        __syncthreads();
#pragma unroll
        for (int kk = 0; kk < 16; kk++) {
            float4 a = *(const float4*)&Hs[kk][mi * 4];
            float4 b = *(const float4*)&Bs[kk][ni * 4];
            float av[4] = {a.x, a.y, a.z, a.w};
            float bv[4] = {b.x, b.y, b.z, b.w};
#pragma unroll
            for (int i = 0; i < 4; i++) {
#pragma unroll
                for (int j = 0; j < 4; j++) {
                    acc[i][j] = fmaf(av[i], bv[j], acc[i][j]);
                }
            }
        }
    }

    const float sc = scale[e];
#pragma unroll
    for (int i = 0; i < 4; i++) {
        int slot = m0 + mi * 4 + i;
        if (slot < cnt) {
            float* yp = &g_y[((size_t)e * T_TOK + slot) * D_DIM + n0 + ni * 4];
            *(float4*)yp = make_float4(acc[i][0] * sc, acc[i][1] * sc,
                                       acc[i][2] * sc, acc[i][3] * sc);
        }
    }
}

// ---------------------------------------------------------------------------
// Kernel 4: weighted combine -> d_out (single deterministic write per element)
// ---------------------------------------------------------------------------
__global__ void combine_kernel(const float* __restrict__ comb,
                               float* __restrict__ out)
{
    int idx = blockIdx.x * blockDim.x + threadIdx.x;
    if (idx >= T_TOK * D_DIM) return;
    int t = idx / D_DIM;
    int d = idx - t * D_DIM;
    float y  = 0.0f;
    int   np = g_np[t];
    for (int j = 0; j < np; j++) {
        int e = g_te[t * E_EXP + j];
        int s = g_ts[t * E_EXP + j];
        y += comb[t * E_EXP + e] * g_y[((size_t)e * T_TOK + s) * D_DIM + d];
    }
    out[idx] = y;
}

// ---------------------------------------------------------------------------
// Launch (graph-capturable: kernel launches only, default stream)
// Inputs (metadata order): tokens, dispatch_weights, combine_weights,
//                          Wg, Wv, Wo, scale
// ---------------------------------------------------------------------------
extern "C" void kernel_launch(void* const* d_in, const int* in_sizes, int n_in,
                              void* d_out, int out_size)
{
    const float* tokens = (const float*)d_in[0];
    const float* disp   = (const float*)d_in[1];
    const float* comb   = (const float*)d_in[2];
    const float* Wg     = (const float*)d_in[3];
    const float* Wv     = (const float*)d_in[4];
    const float* Wo     = (const float*)d_in[5];
    const float* scale  = (const float*)d_in[6];
    float* out = (float*)d_out;

    zero_counts_kernel<<<1, 32>>>();
    build_kernel<<<(T_TOK + 255) / 256, 256>>>(disp);

    dim3 g1(T_TOK / 64, H_DIM / 64, E_EXP);   // (32, 48, 8) — inactive tiles exit
    gemm1_kernel<<<g1, 256>>>(tokens, Wg, Wv);

    dim3 g2(T_TOK / 64, D_DIM / 64, E_EXP);   // (32, 12, 8)
    gemm2_kernel<<<g2, 256>>>(Wo, scale);

    combine_kernel<<<(T_TOK * D_DIM + 255) / 256, 256>>>(comb, out);
}

// round 4
// speedup vs baseline: 3.1526x; 3.1504x over previous
#include <cuda_runtime.h>
#include <math.h>
#include <stdint.h>

// Problem constants (B=2, N=1024 -> T=2048 tokens; D=768; E=8; H=3072; K=2)
#define T_TOK 2048
#define D_DIM 768
#define E_EXP 8
#define H_DIM 3072

// ---------------------------------------------------------------------------
// Static device scratch (allocation-free per harness rules)
// ---------------------------------------------------------------------------
__device__ int   g_count[E_EXP];
__device__ int   g_tok[E_EXP * T_TOK];
__device__ int   g_np[T_TOK];
__device__ int   g_te[T_TOK * E_EXP];
__device__ int   g_ts[T_TOK * E_EXP];
__device__ float g_h[(size_t)E_EXP * T_TOK * H_DIM];     // gelu(gate)*value (tf32-rounded)
__device__ float g_y[(size_t)E_EXP * T_TOK * D_DIM];     // per-pair expert out
__device__ float g_xt[(size_t)T_TOK * D_DIM];            // tf32-rounded tokens
__device__ float g_wgt[(size_t)E_EXP * H_DIM * D_DIM];   // tf32-rounded Wg
__device__ float g_wvt[(size_t)E_EXP * H_DIM * D_DIM];   // tf32-rounded Wv
__device__ float g_wot[(size_t)E_EXP * D_DIM * H_DIM];   // tf32-rounded Wo

// ---------------------------------------------------------------------------
// PTX helpers (all baseline / family-generic: mma.sync sm80+, cp.async sm80+)
// ---------------------------------------------------------------------------
__device__ __forceinline__ float rna1(float f) {
    uint32_t u;
    asm("cvt.rna.tf32.f32 %0, %1;" : "=r"(u) : "f"(f));
    return __uint_as_float(u);
}

#define MMA_TF32(d, a, b)                                                        \
    asm volatile("mma.sync.aligned.m16n8k8.row.col.f32.tf32.tf32.f32 "           \
        "{%0,%1,%2,%3},{%4,%5,%6,%7},{%8,%9},{%0,%1,%2,%3};"                     \
        : "+f"((d)[0]), "+f"((d)[1]), "+f"((d)[2]), "+f"((d)[3])                  \
        : "r"((a)[0]), "r"((a)[1]), "r"((a)[2]), "r"((a)[3]),                     \
          "r"((b)[0]), "r"((b)[1]))

#define CP16(dst, src)                                                           \
    asm volatile("cp.async.cg.shared.global [%0], [%1], 16;"                     \
        :: "r"(dst), "l"(src))
#define CP16Z(dst, src, sz)                                                      \
    asm volatile("cp.async.cg.shared.global [%0], [%1], 16, %2;"                 \
        :: "r"(dst), "l"(src), "r"(sz))
#define CP_COMMIT() asm volatile("cp.async.commit_group;" ::: "memory")
#define CP_WAIT0()  asm volatile("cp.async.wait_group 0;" ::: "memory")
#define CP_WAIT1()  asm volatile("cp.async.wait_group 1;" ::: "memory")

__device__ __forceinline__ uint32_t sm_addr(const void* p) {
    return (uint32_t)__cvta_generic_to_shared(p);
}

// ---------------------------------------------------------------------------
// Routing build (verified in R1)
// ---------------------------------------------------------------------------
__global__ void zero_counts_kernel() {
    int i = threadIdx.x;
    if (i < E_EXP) g_count[i] = 0;
}

__global__ void build_kernel(const float* __restrict__ disp) {
    int t = blockIdx.x * blockDim.x + threadIdx.x;
    if (t >= T_TOK) return;
    int np = 0;
#pragma unroll
    for (int e = 0; e < E_EXP; e++) {
        if (disp[t * E_EXP + e] > 0.0f) {
            int s = atomicAdd(&g_count[e], 1);
            g_tok[e * T_TOK + s] = t;
            g_te[t * E_EXP + np] = e;
            g_ts[t * E_EXP + np] = s;
            np++;
        }
    }
    g_np[t] = np;
}

// ---------------------------------------------------------------------------
// Pre-round fp32 -> tf32 (RNA). One float4 per thread.
// ---------------------------------------------------------------------------
__global__ void cvt4_kernel(const float4* __restrict__ s, float4* __restrict__ d,
                            int n4) {
    int i = blockIdx.x * blockDim.x + threadIdx.x;
    if (i >= n4) return;
    float4 f = s[i];
    d[i] = make_float4(rna1(f.x), rna1(f.y), rna1(f.z), rna1(f.w));
}

// ---------------------------------------------------------------------------
// Shared-memory tiling constants
//   Each chunk matrix tile: 128 rows x 32 k, pitch 36 floats (conflict-free
//   fragment LDS: bank = (36g+tg)%32 = (4g+tg)%32 = lane).
// ---------------------------------------------------------------------------
#define KC     32
#define PITCH  36
#define MATF   (128 * PITCH)      // 4608 floats per matrix tile
#define BUF1F  (3 * MATF)         // gemm1: X, G, V
#define BUF2F  (2 * MATF)         // gemm2: H, W
#define SMEM1  (2 * BUF1F * 4)    // 110592 B
#define SMEM2  (2 * BUF2F * 4)    // 73728 B

// ---------------------------------------------------------------------------
// Stage 1: gate = X@Wg^T, value = X@Wv^T (tf32 mma.sync), fused GELU epilogue.
// Block 128 tokens x 128 H; 8 warps (2 m x 4 n); warp tile 64x32.
// ---------------------------------------------------------------------------
__global__ __launch_bounds__(256) void gemm1_tc(const float* __restrict__ dummy)
{
    extern __shared__ float sm[];
    const int e   = blockIdx.z;
    const int cnt = g_count[e];
    const int m0  = blockIdx.x * 128;
    if (m0 >= cnt) return;
    const int n0  = blockIdx.y * 128;

    const int tid  = threadIdx.x;
    const int lane = tid & 31;
    const int wid  = tid >> 5;
    const int wm   = wid >> 2;        // 0..1
    const int wn   = wid & 3;         // 0..3
    const int g    = lane >> 2;       // 0..7
    const int tg   = lane & 3;        // 0..3

    // ---- load duties: 12 cp.async per thread per chunk ----
    const int seg = tid & 7;                 // float4 segment in 32-k row
    const uint32_t sb = sm_addr(sm);
    const float* xsrc[4]; uint32_t xsz[4]; uint32_t sdst[4];
    const float* gsrc[4]; const float* vsrc[4];
    const size_t ew = (size_t)e * H_DIM * D_DIM;
#pragma unroll
    for (int i = 0; i < 4; i++) {
        int r    = (tid >> 3) + 32 * i;      // 0..127
        int slot = m0 + r;
        bool v   = slot < cnt;
        int tok  = v ? g_tok[e * T_TOK + slot] : 0;
        xsrc[i]  = g_xt + (size_t)tok * D_DIM + seg * 4;
        xsz[i]   = v ? 16u : 0u;
        gsrc[i]  = g_wgt + ew + (size_t)(n0 + r) * D_DIM + seg * 4;
        vsrc[i]  = g_wvt + ew + (size_t)(n0 + r) * D_DIM + seg * 4;
        sdst[i]  = (uint32_t)(r * PITCH + seg * 4) * 4u;
    }

#define G1_LOAD(bsel, k0) do {                                                   \
    uint32_t _b = sb + (uint32_t)(bsel) * (BUF1F * 4);                            \
    _Pragma("unroll")                                                             \
    for (int i = 0; i < 4; i++) {                                                 \
        CP16Z(_b + sdst[i],                (xsrc[i] + (k0)), xsz[i]);             \
        CP16 (_b + MATF * 4 + sdst[i],     (gsrc[i] + (k0)));                     \
        CP16 (_b + 2 * MATF * 4 + sdst[i], (vsrc[i] + (k0)));                     \
    }                                                                             \
    CP_COMMIT();                                                                  \
} while (0)

    float accg[4][4][4] = {};
    float accv[4][4][4] = {};

    const int NIT = D_DIM / KC;   // 24
    G1_LOAD(0, 0);

#pragma unroll 1
    for (int it = 0; it < NIT; ++it) {
        if (it + 1 < NIT) { G1_LOAD((it + 1) & 1, (it + 1) * KC); CP_WAIT1(); }
        else              { CP_WAIT0(); }
        __syncthreads();

        const float* X = sm + (it & 1) * BUF1F + (size_t)(wm * 64 + g) * PITCH + tg;
        const float* G = sm + (it & 1) * BUF1F + MATF
                       + (size_t)(wn * 32 + g) * PITCH + tg;
        const float* V = G + MATF;
#pragma unroll
        for (int kk = 0; kk < KC; kk += 8) {
            uint32_t a[4][4];
#pragma unroll
            for (int fm = 0; fm < 4; fm++) {
                const float* ap = X + fm * 16 * PITCH + kk;
                a[fm][0] = __float_as_uint(ap[0]);
                a[fm][1] = __float_as_uint(ap[8 * PITCH]);
                a[fm][2] = __float_as_uint(ap[4]);
                a[fm][3] = __float_as_uint(ap[8 * PITCH + 4]);
            }
#pragma unroll
            for (int fn = 0; fn < 4; fn++) {
                const float* gp = G + fn * 8 * PITCH + kk;
                const float* vp = V + fn * 8 * PITCH + kk;
                uint32_t bg[2] = { __float_as_uint(gp[0]), __float_as_uint(gp[4]) };
                uint32_t bv[2] = { __float_as_uint(vp[0]), __float_as_uint(vp[4]) };
#pragma unroll
                for (int fm = 0; fm < 4; fm++) {
                    MMA_TF32(accg[fm][fn], a[fm], bg);
                    MMA_TF32(accv[fm][fn], a[fm], bv);
                }
            }
        }
        __syncthreads();
    }

    // ---- epilogue: h = gelu(gate) * value, RNA-rounded for stage 2 ----
#pragma unroll
    for (int fm = 0; fm < 4; fm++) {
        int r0 = m0 + wm * 64 + fm * 16 + g;
        int r1 = r0 + 8;
        float* h0 = g_h + ((size_t)e * T_TOK + r0) * H_DIM;
        float* h1 = g_h + ((size_t)e * T_TOK + r1) * H_DIM;
        bool v0 = r0 < cnt, v1 = r1 < cnt;
#pragma unroll
        for (int fn = 0; fn < 4; fn++) {
            int c = n0 + wn * 32 + fn * 8 + 2 * tg;
            if (v0) {
                float ga = accg[fm][fn][0], gb = accg[fm][fn][1];
                float oa = 0.5f * ga * (1.0f + erff(ga * 0.70710678118654752f))
                         * accv[fm][fn][0];
                float ob = 0.5f * gb * (1.0f + erff(gb * 0.70710678118654752f))
                         * accv[fm][fn][1];
                *(float2*)(h0 + c) = make_float2(rna1(oa), rna1(ob));
            }
            if (v1) {
                float ga = accg[fm][fn][2], gb = accg[fm][fn][3];
                float oa = 0.5f * ga * (1.0f + erff(ga * 0.70710678118654752f))
                         * accv[fm][fn][2];
                float ob = 0.5f * gb * (1.0f + erff(gb * 0.70710678118654752f))
                         * accv[fm][fn][3];
                *(float2*)(h1 + c) = make_float2(rna1(oa), rna1(ob));
            }
        }
    }
    (void)dummy;
}

// ---------------------------------------------------------------------------
// Stage 2: y = scale_e * (h @ Wo^T). Block 128 slots x 128 D, K = 3072.
// ---------------------------------------------------------------------------
__global__ __launch_bounds__(256) void gemm2_tc(const float* __restrict__ scale)
{
    extern __shared__ float sm[];
    const int e   = blockIdx.z;
    const int cnt = g_count[e];
    const int m0  = blockIdx.x * 128;
    if (m0 >= cnt) return;
    const int n0  = blockIdx.y * 128;

    const int tid  = threadIdx.x;
    const int lane = tid & 31;
    const int wid  = tid >> 5;
    const int wm   = wid >> 2;
    const int wn   = wid & 3;
    const int g    = lane >> 2;
    const int tg   = lane & 3;

    const int seg = tid & 7;
    const uint32_t sb = sm_addr(sm);
    const float* asrc[4]; uint32_t asz[4]; const float* bsrc[4]; uint32_t sdst[4];
    const size_t ewo = (size_t)e * D_DIM * H_DIM;
#pragma unroll
    for (int i = 0; i < 4; i++) {
        int r    = (tid >> 3) + 32 * i;
        int slot = m0 + r;
        bool v   = slot < cnt;
        asrc[i]  = g_h + ((size_t)e * T_TOK + (v ? slot : 0)) * H_DIM + seg * 4;
        asz[i]   = v ? 16u : 0u;
        bsrc[i]  = g_wot + ewo + (size_t)(n0 + r) * H_DIM + seg * 4;
        sdst[i]  = (uint32_t)(r * PITCH + seg * 4) * 4u;
    }

#define G2_LOAD(bsel, k0) do {                                                   \
    uint32_t _b = sb + (uint32_t)(bsel) * (BUF2F * 4);                            \
    _Pragma("unroll")                                                             \
    for (int i = 0; i < 4; i++) {                                                 \
        CP16Z(_b + sdst[i],            (asrc[i] + (k0)), asz[i]);                 \
        CP16 (_b + MATF * 4 + sdst[i], (bsrc[i] + (k0)));                         \
    }                                                                             \
    CP_COMMIT();                                                                  \
} while (0)

    float acc[4][4][4] = {};

    const int NIT = H_DIM / KC;   // 96
    G2_LOAD(0, 0);

#pragma unroll 1
    for (int it = 0; it < NIT; ++it) {
        if (it + 1 < NIT) { G2_LOAD((it + 1) & 1, (it + 1) * KC); CP_WAIT1(); }
        else              { CP_WAIT0(); }
        __syncthreads();

        const float* A = sm + (it & 1) * BUF2F + (size_t)(wm * 64 + g) * PITCH + tg;
        const float* Bm = sm + (it & 1) * BUF2F + MATF
                        + (size_t)(wn * 32 + g) * PITCH + tg;
#pragma unroll
        for (int kk = 0; kk < KC; kk += 8) {
            uint32_t a[4][4];
#pragma unroll
            for (int fm = 0; fm < 4; fm++) {
                const float* ap = A + fm * 16 * PITCH + kk;
                a[fm][0] = __float_as_uint(ap[0]);
                a[fm][1] = __float_as_uint(ap[8 * PITCH]);
                a[fm][2] = __float_as_uint(ap[4]);
                a[fm][3] = __float_as_uint(ap[8 * PITCH + 4]);
            }
#pragma unroll
            for (int fn = 0; fn < 4; fn++) {
                const float* bp = Bm + fn * 8 * PITCH + kk;
                uint32_t b[2] = { __float_as_uint(bp[0]), __float_as_uint(bp[4]) };
#pragma unroll
                for (int fm = 0; fm < 4; fm++) {
                    MMA_TF32(acc[fm][fn], a[fm], b);
                }
            }
        }
        __syncthreads();
    }

    const float sc = scale[e];
#pragma unroll
    for (int fm = 0; fm < 4; fm++) {
        int r0 = m0 + wm * 64 + fm * 16 + g;
        int r1 = r0 + 8;
        float* y0 = g_y + ((size_t)e * T_TOK + r0) * D_DIM;
        float* y1 = g_y + ((size_t)e * T_TOK + r1) * D_DIM;
        bool v0 = r0 < cnt, v1 = r1 < cnt;
#pragma unroll
        for (int fn = 0; fn < 4; fn++) {
            int c = n0 + wn * 32 + fn * 8 + 2 * tg;
            if (v0) *(float2*)(y0 + c) =
                make_float2(acc[fm][fn][0] * sc, acc[fm][fn][1] * sc);
            if (v1) *(float2*)(y1 + c) =
                make_float2(acc[fm][fn][2] * sc, acc[fm][fn][3] * sc);
        }
    }
}

// ---------------------------------------------------------------------------
// Combine -> d_out (single deterministic write per element)
// ---------------------------------------------------------------------------
__global__ void combine_kernel(const float* __restrict__ comb,
                               float* __restrict__ out)
{
    int idx = blockIdx.x * blockDim.x + threadIdx.x;
    if (idx >= T_TOK * D_DIM) return;
    int t = idx / D_DIM;
    int d = idx - t * D_DIM;
    float y  = 0.0f;
    int   np = g_np[t];
    for (int j = 0; j < np; j++) {
        int e = g_te[t * E_EXP + j];
        int s = g_ts[t * E_EXP + j];
        y += comb[t * E_EXP + e] * g_y[((size_t)e * T_TOK + s) * D_DIM + d];
    }
    out[idx] = y;
}

// ---------------------------------------------------------------------------
// Launch
// ---------------------------------------------------------------------------
extern "C" void kernel_launch(void* const* d_in, const int* in_sizes, int n_in,
                              void* d_out, int out_size)
{
    const float* tokens = (const float*)d_in[0];
    const float* disp   = (const float*)d_in[1];
    const float* comb   = (const float*)d_in[2];
    const float* Wg     = (const float*)d_in[3];
    const float* Wv     = (const float*)d_in[4];
    const float* Wo     = (const float*)d_in[5];
    const float* scale  = (const float*)d_in[6];
    float* out = (float*)d_out;

    static bool attr_set = false;
    if (!attr_set) {
        cudaFuncSetAttribute(gemm1_tc, cudaFuncAttributeMaxDynamicSharedMemorySize, SMEM1);
        cudaFuncSetAttribute(gemm2_tc, cudaFuncAttributeMaxDynamicSharedMemorySize, SMEM2);
        attr_set = true;
    }

    zero_counts_kernel<<<1, 32>>>();
    build_kernel<<<(T_TOK + 255) / 256, 256>>>(disp);

    // tf32 pre-rounding (RNA) of all GEMM operands
    float* xt;  cudaGetSymbolAddress((void**)&xt,  g_xt);
    float* wgt; cudaGetSymbolAddress((void**)&wgt, g_wgt);
    float* wvt; cudaGetSymbolAddress((void**)&wvt, g_wvt);
    float* wot; cudaGetSymbolAddress((void**)&wot, g_wot);
    {
        int n4 = T_TOK * D_DIM / 4;
        cvt4_kernel<<<(n4 + 255) / 256, 256>>>((const float4*)tokens, (float4*)xt, n4);
    }
    {
        int n4 = E_EXP * H_DIM * D_DIM / 4;
        cvt4_kernel<<<(n4 + 255) / 256, 256>>>((const float4*)Wg, (float4*)wgt, n4);
        cvt4_kernel<<<(n4 + 255) / 256, 256>>>((const float4*)Wv, (float4*)wvt, n4);
        cvt4_kernel<<<(n4 + 255) / 256, 256>>>((const float4*)Wo, (float4*)wot, n4);
    }

    dim3 g1(T_TOK / 128, H_DIM / 128, E_EXP);   // (16, 24, 8)
    gemm1_tc<<<g1, 256, SMEM1>>>(tokens);

    dim3 g2(T_TOK / 128, D_DIM / 128, E_EXP);   // (16, 6, 8)
    gemm2_tc<<<g2, 256, SMEM2>>>(scale);

    combine_kernel<<<(T_TOK * D_DIM + 255) / 256, 256>>>(comb, out);
}

// round 5
// speedup vs baseline: 4.6641x; 1.4795x over previous
#include <cuda_runtime.h>
#include <cuda_fp16.h>
#include <math.h>
#include <stdint.h>

// Problem constants (B=2, N=1024 -> T=2048 tokens; D=768; E=8; H=3072; K=2)
#define T_TOK 2048
#define D_DIM 768
#define E_EXP 8
#define H_DIM 3072

// ---------------------------------------------------------------------------
// Static device scratch (allocation-free per harness rules)
// ---------------------------------------------------------------------------
__device__ int    g_count[E_EXP];
__device__ int    g_tok[E_EXP * T_TOK];
__device__ int    g_np[T_TOK];
__device__ int    g_te[T_TOK * E_EXP];
__device__ int    g_ts[T_TOK * E_EXP];
__device__ __half g_hh[(size_t)E_EXP * T_TOK * H_DIM];    // gelu(gate)*value, fp16
__device__ float  g_y[(size_t)E_EXP * T_TOK * D_DIM];     // per-pair expert out
__device__ __half g_xh[(size_t)T_TOK * D_DIM];            // fp16 tokens
__device__ __half g_wgh[(size_t)E_EXP * H_DIM * D_DIM];   // fp16 Wg
__device__ __half g_wvh[(size_t)E_EXP * H_DIM * D_DIM];   // fp16 Wv
__device__ __half g_woh[(size_t)E_EXP * D_DIM * H_DIM];   // fp16 Wo * scale_e

// ---------------------------------------------------------------------------
// PTX helpers (family-generic: mma.sync sm80+, cp.async sm80+)
// ---------------------------------------------------------------------------
#define MMA_F16(d, a, b)                                                         \
    asm volatile("mma.sync.aligned.m16n8k16.row.col.f32.f16.f16.f32 "            \
        "{%0,%1,%2,%3},{%4,%5,%6,%7},{%8,%9},{%0,%1,%2,%3};"                     \
        : "+f"((d)[0]), "+f"((d)[1]), "+f"((d)[2]), "+f"((d)[3])                  \
        : "r"((a)[0]), "r"((a)[1]), "r"((a)[2]), "r"((a)[3]),                     \
          "r"((b)[0]), "r"((b)[1]))

#define CP16(dst, src)                                                           \
    asm volatile("cp.async.cg.shared.global [%0], [%1], 16;"                     \
        :: "r"(dst), "l"(src))
#define CP16Z(dst, src, sz)                                                      \
    asm volatile("cp.async.cg.shared.global [%0], [%1], 16, %2;"                 \
        :: "r"(dst), "l"(src), "r"(sz))
#define CP_COMMIT() asm volatile("cp.async.commit_group;" ::: "memory")
#define CP_WAIT0()  asm volatile("cp.async.wait_group 0;" ::: "memory")
#define CP_WAIT1()  asm volatile("cp.async.wait_group 1;" ::: "memory")

__device__ __forceinline__ uint32_t sm_addr(const void* p) {
    return (uint32_t)__cvta_generic_to_shared(p);
}
__device__ __forceinline__ uint32_t ld_u32(const __half* p) {
    return *(const uint32_t*)p;
}

// ---------------------------------------------------------------------------
// Routing build (verified R1)
// ---------------------------------------------------------------------------
__global__ void zero_counts_kernel() {
    int i = threadIdx.x;
    if (i < E_EXP) g_count[i] = 0;
}

__global__ void build_kernel(const float* __restrict__ disp) {
    int t = blockIdx.x * blockDim.x + threadIdx.x;
    if (t >= T_TOK) return;
    int np = 0;
#pragma unroll
    for (int e = 0; e < E_EXP; e++) {
        if (disp[t * E_EXP + e] > 0.0f) {
            int s = atomicAdd(&g_count[e], 1);
            g_tok[e * T_TOK + s] = t;
            g_te[t * E_EXP + np] = e;
            g_ts[t * E_EXP + np] = s;
            np++;
        }
    }
    g_np[t] = np;
}

// ---------------------------------------------------------------------------
// fp32 -> fp16 conversion (RN). 4 elements per thread.
// ---------------------------------------------------------------------------
__global__ void cvt_h_kernel(const float4* __restrict__ s,
                             uint2* __restrict__ d, int n4) {
    int i = blockIdx.x * blockDim.x + threadIdx.x;
    if (i >= n4) return;
    float4 f = s[i];
    __half2 h01 = __floats2half2_rn(f.x, f.y);
    __half2 h23 = __floats2half2_rn(f.z, f.w);
    uint2 u;
    u.x = *(const uint32_t*)&h01;
    u.y = *(const uint32_t*)&h23;
    d[i] = u;
}

// Wo conversion with scale_e folded in (scale = 1/E, exact in premultiply)
__global__ void cvt_wo_kernel(const float4* __restrict__ s,
                              uint2* __restrict__ d,
                              const float* __restrict__ scale, int n4) {
    int i = blockIdx.x * blockDim.x + threadIdx.x;
    if (i >= n4) return;
    int e = (int)(((size_t)i * 4) / ((size_t)D_DIM * H_DIM));
    float sc = scale[e];
    float4 f = s[i];
    __half2 h01 = __floats2half2_rn(f.x * sc, f.y * sc);
    __half2 h23 = __floats2half2_rn(f.z * sc, f.w * sc);
    uint2 u;
    u.x = *(const uint32_t*)&h01;
    u.y = *(const uint32_t*)&h23;
    d[i] = u;
}

// ---------------------------------------------------------------------------
// Tiling: block 128x128, 8 warps (2m x 4n), warp tile 64x32, KC = 32 halves.
// smem matrix tile: 128 rows x pitch 40 halves = 10240 B (conflict-free:
// fragment LDS bank = (20g+tg)%32, all distinct within a warp).
// ---------------------------------------------------------------------------
#define KC    32
#define PH    40
#define MATB  (128 * PH * 2)        // 10240 B
#define BUF1B (3 * MATB)            // X, G, V
#define BUF2B (2 * MATB)            // H, W
#define SMEM1 (2 * BUF1B)           // 61440 B
#define SMEM2 (2 * BUF2B)           // 40960 B

// ---------------------------------------------------------------------------
// Stage 1: gate = X@Wg^T, value = X@Wv^T (fp16 mma), fused GELU epilogue.
// ---------------------------------------------------------------------------
__global__ __launch_bounds__(256) void gemm1_tc()
{
    extern __shared__ __half smh[];
    const int e   = blockIdx.z;
    const int cnt = g_count[e];
    const int m0  = blockIdx.x * 128;
    if (m0 >= cnt) return;
    const int n0  = blockIdx.y * 128;

    const int tid  = threadIdx.x;
    const int lane = tid & 31;
    const int wid  = tid >> 5;
    const int wm   = wid >> 2;        // 0..1
    const int wn   = wid & 3;         // 0..3
    const int g    = lane >> 2;       // 0..7
    const int tg   = lane & 3;        // 0..3

    // ---- load duties: 6 cp.async (16B) per thread per chunk ----
    const int seg = tid & 3;                 // 16B segment within 64B row
    const uint32_t sb = sm_addr(smh);
    const __half* xsrc[2]; uint32_t xsz[2]; uint32_t sdst[2];
    const __half* gsrc[2]; const __half* vsrc[2];
    const size_t ew = (size_t)e * H_DIM * D_DIM;
#pragma unroll
    for (int i = 0; i < 2; i++) {
        int r    = (tid >> 2) + 64 * i;      // 0..127
        int slot = m0 + r;
        bool v   = slot < cnt;
        int tok  = v ? g_tok[e * T_TOK + slot] : 0;
        xsrc[i]  = g_xh + (size_t)tok * D_DIM + seg * 8;
        xsz[i]   = v ? 16u : 0u;
        gsrc[i]  = g_wgh + ew + (size_t)(n0 + r) * D_DIM + seg * 8;
        vsrc[i]  = g_wvh + ew + (size_t)(n0 + r) * D_DIM + seg * 8;
        sdst[i]  = (uint32_t)(r * PH + seg * 8) * 2u;
    }

#define G1_LOAD(bsel, k0) do {                                                   \
    uint32_t _b = sb + (uint32_t)(bsel) * BUF1B;                                  \
    _Pragma("unroll")                                                             \
    for (int i = 0; i < 2; i++) {                                                 \
        CP16Z(_b + sdst[i],            (xsrc[i] + (k0)), xsz[i]);                 \
        CP16 (_b + MATB + sdst[i],     (gsrc[i] + (k0)));                         \
        CP16 (_b + 2 * MATB + sdst[i], (vsrc[i] + (k0)));                         \
    }                                                                             \
    CP_COMMIT();                                                                  \
} while (0)

    float accg[4][4][4] = {};
    float accv[4][4][4] = {};

    const int NIT = D_DIM / KC;   // 24
    G1_LOAD(0, 0);

#pragma unroll 1
    for (int it = 0; it < NIT; ++it) {
        if (it + 1 < NIT) { G1_LOAD((it + 1) & 1, (it + 1) * KC); CP_WAIT1(); }
        else              { CP_WAIT0(); }
        __syncthreads();

        const __half* X = smh + (it & 1) * (BUF1B / 2)
                        + (size_t)(wm * 64 + g) * PH + 2 * tg;
        const __half* G = smh + (it & 1) * (BUF1B / 2) + (MATB / 2)
                        + (size_t)(wn * 32 + g) * PH + 2 * tg;
        const __half* V = G + (MATB / 2);
#pragma unroll
        for (int ks = 0; ks < 2; ks++) {
            const int k0 = ks * 16;
            uint32_t a[4][4];
#pragma unroll
            for (int fm = 0; fm < 4; fm++) {
                const __half* ap = X + fm * 16 * PH + k0;
                a[fm][0] = ld_u32(ap);
                a[fm][1] = ld_u32(ap + 8 * PH);
                a[fm][2] = ld_u32(ap + 8);
                a[fm][3] = ld_u32(ap + 8 * PH + 8);
            }
#pragma unroll
            for (int fn = 0; fn < 4; fn++) {
                const __half* gp = G + fn * 8 * PH + k0;
                const __half* vp = V + fn * 8 * PH + k0;
                uint32_t bg[2] = { ld_u32(gp), ld_u32(gp + 8) };
                uint32_t bv[2] = { ld_u32(vp), ld_u32(vp + 8) };
#pragma unroll
                for (int fm = 0; fm < 4; fm++) {
                    MMA_F16(accg[fm][fn], a[fm], bg);
                    MMA_F16(accv[fm][fn], a[fm], bv);
                }
            }
        }
        __syncthreads();
    }

    // ---- epilogue: h = gelu(gate) * value -> fp16 ----
#pragma unroll
    for (int fm = 0; fm < 4; fm++) {
        int r0 = m0 + wm * 64 + fm * 16 + g;
        int r1 = r0 + 8;
        __half* h0 = g_hh + ((size_t)e * T_TOK + r0) * H_DIM;
        __half* h1 = g_hh + ((size_t)e * T_TOK + r1) * H_DIM;
        bool v0 = r0 < cnt, v1 = r1 < cnt;
#pragma unroll
        for (int fn = 0; fn < 4; fn++) {
            int c = n0 + wn * 32 + fn * 8 + 2 * tg;
            if (v0) {
                float ga = accg[fm][fn][0], gb = accg[fm][fn][1];
                float oa = 0.5f * ga * (1.0f + erff(ga * 0.70710678118654752f))
                         * accv[fm][fn][0];
                float ob = 0.5f * gb * (1.0f + erff(gb * 0.70710678118654752f))
                         * accv[fm][fn][1];
                *(__half2*)(h0 + c) = __floats2half2_rn(oa, ob);
            }
            if (v1) {
                float ga = accg[fm][fn][2], gb = accg[fm][fn][3];
                float oa = 0.5f * ga * (1.0f + erff(ga * 0.70710678118654752f))
                         * accv[fm][fn][2];
                float ob = 0.5f * gb * (1.0f + erff(gb * 0.70710678118654752f))
                         * accv[fm][fn][3];
                *(__half2*)(h1 + c) = __floats2half2_rn(oa, ob);
            }
        }
    }
}

// ---------------------------------------------------------------------------
// Stage 2: y = h @ (Wo*scale)^T. Block 128 x 128, K = 3072.
// ---------------------------------------------------------------------------
__global__ __launch_bounds__(256) void gemm2_tc()
{
    extern __shared__ __half smh[];
    const int e   = blockIdx.z;
    const int cnt = g_count[e];
    const int m0  = blockIdx.x * 128;
    if (m0 >= cnt) return;
    const int n0  = blockIdx.y * 128;

    const int tid  = threadIdx.x;
    const int lane = tid & 31;
    const int wid  = tid >> 5;
    const int wm   = wid >> 2;
    const int wn   = wid & 3;
    const int g    = lane >> 2;
    const int tg   = lane & 3;

    const int seg = tid & 3;
    const uint32_t sb = sm_addr(smh);
    const __half* asrc[2]; uint32_t asz[2]; const __half* bsrc[2]; uint32_t sdst[2];
    const size_t ewo = (size_t)e * D_DIM * H_DIM;
#pragma unroll
    for (int i = 0; i < 2; i++) {
        int r    = (tid >> 2) + 64 * i;
        int slot = m0 + r;
        bool v   = slot < cnt;
        asrc[i]  = g_hh + ((size_t)e * T_TOK + (v ? slot : 0)) * H_DIM + seg * 8;
        asz[i]   = v ? 16u : 0u;
        bsrc[i]  = g_woh + ewo + (size_t)(n0 + r) * H_DIM + seg * 8;
        sdst[i]  = (uint32_t)(r * PH + seg * 8) * 2u;
    }

#define G2_LOAD(bsel, k0) do {                                                   \
    uint32_t _b = sb + (uint32_t)(bsel) * BUF2B;                                  \
    _Pragma("unroll")                                                             \
    for (int i = 0; i < 2; i++) {                                                 \
        CP16Z(_b + sdst[i],        (asrc[i] + (k0)), asz[i]);                     \
        CP16 (_b + MATB + sdst[i], (bsrc[i] + (k0)));                             \
    }                                                                             \
    CP_COMMIT();                                                                  \
} while (0)

    float acc[4][4][4] = {};

    const int NIT = H_DIM / KC;   // 96
    G2_LOAD(0, 0);

#pragma unroll 1
    for (int it = 0; it < NIT; ++it) {
        if (it + 1 < NIT) { G2_LOAD((it + 1) & 1, (it + 1) * KC); CP_WAIT1(); }
        else              { CP_WAIT0(); }
        __syncthreads();

        const __half* A = smh + (it & 1) * (BUF2B / 2)
                        + (size_t)(wm * 64 + g) * PH + 2 * tg;
        const __half* Bm = smh + (it & 1) * (BUF2B / 2) + (MATB / 2)
                         + (size_t)(wn * 32 + g) * PH + 2 * tg;
#pragma unroll
        for (int ks = 0; ks < 2; ks++) {
            const int k0 = ks * 16;
            uint32_t a[4][4];
#pragma unroll
            for (int fm = 0; fm < 4; fm++) {
                const __half* ap = A + fm * 16 * PH + k0;
                a[fm][0] = ld_u32(ap);
                a[fm][1] = ld_u32(ap + 8 * PH);
                a[fm][2] = ld_u32(ap + 8);
                a[fm][3] = ld_u32(ap + 8 * PH + 8);
            }
#pragma unroll
            for (int fn = 0; fn < 4; fn++) {
                const __half* bp = Bm + fn * 8 * PH + k0;
                uint32_t b[2] = { ld_u32(bp), ld_u32(bp + 8) };
#pragma unroll
                for (int fm = 0; fm < 4; fm++) {
                    MMA_F16(acc[fm][fn], a[fm], b);
                }
            }
        }
        __syncthreads();
    }

#pragma unroll
    for (int fm = 0; fm < 4; fm++) {
        int r0 = m0 + wm * 64 + fm * 16 + g;
        int r1 = r0 + 8;
        float* y0 = g_y + ((size_t)e * T_TOK + r0) * D_DIM;
        float* y1 = g_y + ((size_t)e * T_TOK + r1) * D_DIM;
        bool v0 = r0 < cnt, v1 = r1 < cnt;
#pragma unroll
        for (int fn = 0; fn < 4; fn++) {
            int c = n0 + wn * 32 + fn * 8 + 2 * tg;
            if (v0) *(float2*)(y0 + c) =
                make_float2(acc[fm][fn][0], acc[fm][fn][1]);
            if (v1) *(float2*)(y1 + c) =
                make_float2(acc[fm][fn][2], acc[fm][fn][3]);
        }
    }
}

// ---------------------------------------------------------------------------
// Combine -> d_out (single deterministic write per element)
// ---------------------------------------------------------------------------
__global__ void combine_kernel(const float* __restrict__ comb,
                               float* __restrict__ out)
{
    int idx = blockIdx.x * blockDim.x + threadIdx.x;
    if (idx >= T_TOK * D_DIM) return;
    int t = idx / D_DIM;
    int d = idx - t * D_DIM;
    float y  = 0.0f;
    int   np = g_np[t];
    for (int j = 0; j < np; j++) {
        int e = g_te[t * E_EXP + j];
        int s = g_ts[t * E_EXP + j];
        y += comb[t * E_EXP + e] * g_y[((size_t)e * T_TOK + s) * D_DIM + d];
    }
    out[idx] = y;
}

// ---------------------------------------------------------------------------
// Launch
// ---------------------------------------------------------------------------
extern "C" void kernel_launch(void* const* d_in, const int* in_sizes, int n_in,
                              void* d_out, int out_size)
{
    const float* tokens = (const float*)d_in[0];
    const float* disp   = (const float*)d_in[1];
    const float* comb   = (const float*)d_in[2];
    const float* Wg     = (const float*)d_in[3];
    const float* Wv     = (const float*)d_in[4];
    const float* Wo     = (const float*)d_in[5];
    const float* scale  = (const float*)d_in[6];
    float* out = (float*)d_out;

    static bool attr_set = false;
    if (!attr_set) {
        cudaFuncSetAttribute(gemm1_tc, cudaFuncAttributeMaxDynamicSharedMemorySize, SMEM1);
        cudaFuncSetAttribute(gemm2_tc, cudaFuncAttributeMaxDynamicSharedMemorySize, SMEM2);
        attr_set = true;
    }

    zero_counts_kernel<<<1, 32>>>();
    build_kernel<<<(T_TOK + 255) / 256, 256>>>(disp);

    // fp16 conversion of all GEMM operands
    __half* xh;  cudaGetSymbolAddress((void**)&xh,  g_xh);
    __half* wgh; cudaGetSymbolAddress((void**)&wgh, g_wgh);
    __half* wvh; cudaGetSymbolAddress((void**)&wvh, g_wvh);
    __half* woh; cudaGetSymbolAddress((void**)&woh, g_woh);
    {
        int n4 = T_TOK * D_DIM / 4;
        cvt_h_kernel<<<(n4 + 255) / 256, 256>>>((const float4*)tokens, (uint2*)xh, n4);
    }
    {
        int n4 = E_EXP * H_DIM * D_DIM / 4;
        cvt_h_kernel<<<(n4 + 255) / 256, 256>>>((const float4*)Wg, (uint2*)wgh, n4);
        cvt_h_kernel<<<(n4 + 255) / 256, 256>>>((const float4*)Wv, (uint2*)wvh, n4);
        cvt_wo_kernel<<<(n4 + 255) / 256, 256>>>((const float4*)Wo, (uint2*)woh, scale, n4);
    }

    dim3 g1(T_TOK / 128, H_DIM / 128, E_EXP);   // (16, 24, 8)
    gemm1_tc<<<g1, 256, SMEM1>>>();

    dim3 g2(T_TOK / 128, D_DIM / 128, E_EXP);   // (16, 6, 8)
    gemm2_tc<<<g2, 256, SMEM2>>>();

    combine_kernel<<<(T_TOK * D_DIM + 255) / 256, 256>>>(comb, out);
}

// round 6
// speedup vs baseline: 5.4214x; 1.1624x over previous
#include <cuda_runtime.h>
#include <cuda_fp16.h>
#include <math.h>
#include <stdint.h>

// Problem constants (B=2, N=1024 -> T=2048 tokens; D=768; E=8; H=3072; K=2)
#define T_TOK 2048
#define D_DIM 768
#define E_EXP 8
#define H_DIM 3072

// ---------------------------------------------------------------------------
// Static device scratch (allocation-free per harness rules)
// ---------------------------------------------------------------------------
__device__ int    g_count[E_EXP];
__device__ int    g_tok[E_EXP * T_TOK];
__device__ int    g_np[T_TOK];
__device__ int    g_te[T_TOK * E_EXP];
__device__ int    g_ts[T_TOK * E_EXP];
__device__ __half g_hh[(size_t)E_EXP * T_TOK * H_DIM];    // gelu(gate)*value, fp16
__device__ float  g_y[(size_t)E_EXP * T_TOK * D_DIM];     // per-pair expert out
__device__ __half g_xh[(size_t)T_TOK * D_DIM];            // fp16 tokens
__device__ __half g_wgh[(size_t)E_EXP * H_DIM * D_DIM];   // fp16 Wg
__device__ __half g_wvh[(size_t)E_EXP * H_DIM * D_DIM];   // fp16 Wv
__device__ __half g_woh[(size_t)E_EXP * D_DIM * H_DIM];   // fp16 Wo * scale_e

// ---------------------------------------------------------------------------
// PTX helpers (family-generic: mma.sync sm80+, ldmatrix sm75+, cp.async sm80+)
// ---------------------------------------------------------------------------
#define MMA_F16(d, a, b)                                                         \
    asm volatile("mma.sync.aligned.m16n8k16.row.col.f32.f16.f16.f32 "            \
        "{%0,%1,%2,%3},{%4,%5,%6,%7},{%8,%9},{%0,%1,%2,%3};"                     \
        : "+f"((d)[0]), "+f"((d)[1]), "+f"((d)[2]), "+f"((d)[3])                  \
        : "r"((a)[0]), "r"((a)[1]), "r"((a)[2]), "r"((a)[3]),                     \
          "r"((b)[0]), "r"((b)[1]))

#define LDSM4(r, addr)                                                           \
    asm volatile("ldmatrix.sync.aligned.m8n8.x4.shared.b16 {%0,%1,%2,%3}, [%4];" \
        : "=r"((r)[0]), "=r"((r)[1]), "=r"((r)[2]), "=r"((r)[3]) : "r"(addr))
#define LDSM2(r, addr)                                                           \
    asm volatile("ldmatrix.sync.aligned.m8n8.x2.shared.b16 {%0,%1}, [%2];"       \
        : "=r"((r)[0]), "=r"((r)[1]) : "r"(addr))

#define CP16(dst, src)                                                           \
    asm volatile("cp.async.cg.shared.global [%0], [%1], 16;"                     \
        :: "r"(dst), "l"(src))
#define CP16Z(dst, src, sz)                                                      \
    asm volatile("cp.async.cg.shared.global [%0], [%1], 16, %2;"                 \
        :: "r"(dst), "l"(src), "r"(sz))
#define CP_COMMIT() asm volatile("cp.async.commit_group;" ::: "memory")
#define CP_WAIT0()  asm volatile("cp.async.wait_group 0;" ::: "memory")
#define CP_WAIT1()  asm volatile("cp.async.wait_group 1;" ::: "memory")

__device__ __forceinline__ uint32_t sm_addr(const void* p) {
    return (uint32_t)__cvta_generic_to_shared(p);
}

// ---------------------------------------------------------------------------
// Routing build (verified R1)
// ---------------------------------------------------------------------------
__global__ void zero_counts_kernel() {
    int i = threadIdx.x;
    if (i < E_EXP) g_count[i] = 0;
}

__global__ void build_kernel(const float* __restrict__ disp) {
    int t = blockIdx.x * blockDim.x + threadIdx.x;
    if (t >= T_TOK) return;
    int np = 0;
#pragma unroll
    for (int e = 0; e < E_EXP; e++) {
        if (disp[t * E_EXP + e] > 0.0f) {
            int s = atomicAdd(&g_count[e], 1);
            g_tok[e * T_TOK + s] = t;
            g_te[t * E_EXP + np] = e;
            g_ts[t * E_EXP + np] = s;
            np++;
        }
    }
    g_np[t] = np;
}

// ---------------------------------------------------------------------------
// Fused fp32 -> fp16 conversion of all GEMM operands (single launch).
// Regions: [tokens | Wg | Wv | Wo*scale], each float4-indexed.
// ---------------------------------------------------------------------------
#define X4  (T_TOK * D_DIM / 4)            // 393216
#define W4  (E_EXP * H_DIM * D_DIM / 4)    // 4718592
#define EW4 (D_DIM * H_DIM / 4)            // 589824 (per-expert Wo float4s)

__global__ void cvt_all_kernel(const float4* __restrict__ tok,
                               const float4* __restrict__ wg,
                               const float4* __restrict__ wv,
                               const float4* __restrict__ wo,
                               const float*  __restrict__ scale,
                               uint2* __restrict__ xh, uint2* __restrict__ wgh,
                               uint2* __restrict__ wvh, uint2* __restrict__ woh)
{
    int i = blockIdx.x * blockDim.x + threadIdx.x;
    float4 f; uint2* dst; float sc = 1.0f;
    if (i < X4)                 { f = tok[i];          dst = xh  + i; }
    else {
        int j = i - X4;
        if (j < W4)             { f = wg[j];           dst = wgh + j; }
        else if (j < 2 * W4)    { j -= 2 * W4 - W4; j -= W4 - W4; j = i - X4 - W4;
                                  f = wv[j];           dst = wvh + j; }
        else if (j < 3 * W4)    { j = i - X4 - 2 * W4;
                                  f = wo[j];           dst = woh + j;
                                  sc = scale[j / EW4]; }
        else return;
    }
    __half2 h01 = __floats2half2_rn(f.x * sc, f.y * sc);
    __half2 h23 = __floats2half2_rn(f.z * sc, f.w * sc);
    uint2 u;
    u.x = *(const uint32_t*)&h01;
    u.y = *(const uint32_t*)&h23;
    *dst = u;
}

// ---------------------------------------------------------------------------
// Tiling: block 128x128, 8 warps (2m x 4n), warp tile 64x32, KC = 64 halves.
// smem tile: 128 rows x pitch 72 halves (ldmatrix 8-row phases conflict-free:
// (36r)%32 distinct for r=0..7).
// ---------------------------------------------------------------------------
#define KC    64
#define PH    72
#define MATB  (128 * PH * 2)        // 18432 B
#define BUF1B (3 * MATB)            // X, G, V  (55296 B)
#define BUF2B (2 * MATB)            // H, W     (36864 B)
#define SMEM1 (2 * BUF1B)           // 110592 B
#define SMEM2 (2 * BUF2B)           // 73728 B

// ---------------------------------------------------------------------------
// Stage 1: gate = X@Wg^T, value = X@Wv^T (fp16 mma), fused GELU epilogue.
// ---------------------------------------------------------------------------
__global__ __launch_bounds__(256) void gemm1_tc()
{
    extern __shared__ __half smh[];
    const int e   = blockIdx.z;
    const int cnt = g_count[e];
    const int m0  = blockIdx.x * 128;
    if (m0 >= cnt) return;
    const int n0  = blockIdx.y * 128;

    const int tid  = threadIdx.x;
    const int lane = tid & 31;
    const int wid  = tid >> 5;
    const int wm   = wid >> 2;        // 0..1
    const int wn   = wid & 3;         // 0..3
    const int g    = lane >> 2;       // 0..7
    const int tg   = lane & 3;        // 0..3

    // ---- load duties: 12 cp.async (16B) per thread per 64-k chunk ----
    const int seg = tid & 7;                 // 16B segment within 128B row
    const uint32_t sb = sm_addr(smh);
    const __half* xsrc[4]; uint32_t xsz[4]; uint32_t sdst[4];
    const __half* gsrc[4]; const __half* vsrc[4];
    const size_t ew = (size_t)e * H_DIM * D_DIM;
#pragma unroll
    for (int i = 0; i < 4; i++) {
        int r    = (tid >> 3) + 32 * i;      // 0..127
        int slot = m0 + r;
        bool v   = slot < cnt;
        int tok  = v ? g_tok[e * T_TOK + slot] : 0;
        xsrc[i]  = g_xh + (size_t)tok * D_DIM + seg * 8;
        xsz[i]   = v ? 16u : 0u;
        gsrc[i]  = g_wgh + ew + (size_t)(n0 + r) * D_DIM + seg * 8;
        vsrc[i]  = g_wvh + ew + (size_t)(n0 + r) * D_DIM + seg * 8;
        sdst[i]  = (uint32_t)(r * PH + seg * 8) * 2u;
    }

#define G1_LOAD(bsel, k0) do {                                                   \
    uint32_t _b = sb + (uint32_t)(bsel) * BUF1B;                                  \
    _Pragma("unroll")                                                             \
    for (int i = 0; i < 4; i++) {                                                 \
        CP16Z(_b + sdst[i],            (xsrc[i] + (k0)), xsz[i]);                 \
        CP16 (_b + MATB + sdst[i],     (gsrc[i] + (k0)));                         \
        CP16 (_b + 2 * MATB + sdst[i], (vsrc[i] + (k0)));                         \
    }                                                                             \
    CP_COMMIT();                                                                  \
} while (0)

    // ldmatrix lane bases (byte offsets into a tile)
    const uint32_t aoff = (uint32_t)((wm * 64 + (lane & 15)) * PH
                                     + ((lane >> 4) * 8)) * 2u;
    const uint32_t boff = (uint32_t)((wn * 32 + (lane & 7)) * PH
                                     + (((lane >> 3) & 1) * 8)) * 2u;

    float accg[4][4][4] = {};
    float accv[4][4][4] = {};

    const int NIT = D_DIM / KC;   // 12
    G1_LOAD(0, 0);

#pragma unroll 1
    for (int it = 0; it < NIT; ++it) {
        if (it + 1 < NIT) { G1_LOAD((it + 1) & 1, (it + 1) * KC); CP_WAIT1(); }
        else              { CP_WAIT0(); }
        __syncthreads();

        const uint32_t ba = sb + (it & 1) * BUF1B;
        const uint32_t Xa = ba + aoff;
        const uint32_t Ga = ba + MATB + boff;
        const uint32_t Va = ba + 2 * MATB + boff;
#pragma unroll
        for (int ks = 0; ks < 4; ks++) {
            const uint32_t kb = ks * 32;           // 16 halves = 32 bytes
            uint32_t a[4][4];
#pragma unroll
            for (int fm = 0; fm < 4; fm++)
                LDSM4(a[fm], Xa + fm * (16 * PH * 2) + kb);
#pragma unroll
            for (int fn = 0; fn < 4; fn++) {
                uint32_t bg[2], bv[2];
                LDSM2(bg, Ga + fn * (8 * PH * 2) + kb);
                LDSM2(bv, Va + fn * (8 * PH * 2) + kb);
#pragma unroll
                for (int fm = 0; fm < 4; fm++) {
                    MMA_F16(accg[fm][fn], a[fm], bg);
                    MMA_F16(accv[fm][fn], a[fm], bv);
                }
            }
        }
        __syncthreads();
    }

    // ---- epilogue: h = gelu(gate) * value -> fp16 ----
#pragma unroll
    for (int fm = 0; fm < 4; fm++) {
        int r0 = m0 + wm * 64 + fm * 16 + g;
        int r1 = r0 + 8;
        __half* h0 = g_hh + ((size_t)e * T_TOK + r0) * H_DIM;
        __half* h1 = g_hh + ((size_t)e * T_TOK + r1) * H_DIM;
        bool v0 = r0 < cnt, v1 = r1 < cnt;
#pragma unroll
        for (int fn = 0; fn < 4; fn++) {
            int c = n0 + wn * 32 + fn * 8 + 2 * tg;
            if (v0) {
                float ga = accg[fm][fn][0], gb = accg[fm][fn][1];
                float oa = 0.5f * ga * (1.0f + erff(ga * 0.70710678118654752f))
                         * accv[fm][fn][0];
                float ob = 0.5f * gb * (1.0f + erff(gb * 0.70710678118654752f))
                         * accv[fm][fn][1];
                *(__half2*)(h0 + c) = __floats2half2_rn(oa, ob);
            }
            if (v1) {
                float ga = accg[fm][fn][2], gb = accg[fm][fn][3];
                float oa = 0.5f * ga * (1.0f + erff(ga * 0.70710678118654752f))
                         * accv[fm][fn][2];
                float ob = 0.5f * gb * (1.0f + erff(gb * 0.70710678118654752f))
                         * accv[fm][fn][3];
                *(__half2*)(h1 + c) = __floats2half2_rn(oa, ob);
            }
        }
    }
}

// ---------------------------------------------------------------------------
// Stage 2: y = h @ (Wo*scale)^T. Block 128 x 128, K = 3072.
// ---------------------------------------------------------------------------
__global__ __launch_bounds__(256) void gemm2_tc()
{
    extern __shared__ __half smh[];
    const int e   = blockIdx.z;
    const int cnt = g_count[e];
    const int m0  = blockIdx.x * 128;
    if (m0 >= cnt) return;
    const int n0  = blockIdx.y * 128;

    const int tid  = threadIdx.x;
    const int lane = tid & 31;
    const int wid  = tid >> 5;
    const int wm   = wid >> 2;
    const int wn   = wid & 3;
    const int g    = lane >> 2;
    const int tg   = lane & 3;

    const int seg = tid & 7;
    const uint32_t sb = sm_addr(smh);
    const __half* asrc[4]; uint32_t asz[4]; const __half* bsrc[4]; uint32_t sdst[4];
    const size_t ewo = (size_t)e * D_DIM * H_DIM;
#pragma unroll
    for (int i = 0; i < 4; i++) {
        int r    = (tid >> 3) + 32 * i;
        int slot = m0 + r;
        bool v   = slot < cnt;
        asrc[i]  = g_hh + ((size_t)e * T_TOK + (v ? slot : 0)) * H_DIM + seg * 8;
        asz[i]   = v ? 16u : 0u;
        bsrc[i]  = g_woh + ewo + (size_t)(n0 + r) * H_DIM + seg * 8;
        sdst[i]  = (uint32_t)(r * PH + seg * 8) * 2u;
    }

#define G2_LOAD(bsel, k0) do {                                                   \
    uint32_t _b = sb + (uint32_t)(bsel) * BUF2B;                                  \
    _Pragma("unroll")                                                             \
    for (int i = 0; i < 4; i++) {                                                 \
        CP16Z(_b + sdst[i],        (asrc[i] + (k0)), asz[i]);                     \
        CP16 (_b + MATB + sdst[i], (bsrc[i] + (k0)));                             \
    }                                                                             \
    CP_COMMIT();                                                                  \
} while (0)

    const uint32_t aoff = (uint32_t)((wm * 64 + (lane & 15)) * PH
                                     + ((lane >> 4) * 8)) * 2u;
    const uint32_t boff = (uint32_t)((wn * 32 + (lane & 7)) * PH
                                     + (((lane >> 3) & 1) * 8)) * 2u;

    float acc[4][4][4] = {};

    const int NIT = H_DIM / KC;   // 48
    G2_LOAD(0, 0);

#pragma unroll 1
    for (int it = 0; it < NIT; ++it) {
        if (it + 1 < NIT) { G2_LOAD((it + 1) & 1, (it + 1) * KC); CP_WAIT1(); }
        else              { CP_WAIT0(); }
        __syncthreads();

        const uint32_t ba = sb + (it & 1) * BUF2B;
        const uint32_t Aa = ba + aoff;
        const uint32_t Ba = ba + MATB + boff;
#pragma unroll
        for (int ks = 0; ks < 4; ks++) {
            const uint32_t kb = ks * 32;
            uint32_t a[4][4];
#pragma unroll
            for (int fm = 0; fm < 4; fm++)
                LDSM4(a[fm], Aa + fm * (16 * PH * 2) + kb);
#pragma unroll
            for (int fn = 0; fn < 4; fn++) {
                uint32_t b[2];
                LDSM2(b, Ba + fn * (8 * PH * 2) + kb);
#pragma unroll
                for (int fm = 0; fm < 4; fm++)
                    MMA_F16(acc[fm][fn], a[fm], b);
            }
        }
        __syncthreads();
    }

#pragma unroll
    for (int fm = 0; fm < 4; fm++) {
        int r0 = m0 + wm * 64 + fm * 16 + g;
        int r1 = r0 + 8;
        float* y0 = g_y + ((size_t)e * T_TOK + r0) * D_DIM;
        float* y1 = g_y + ((size_t)e * T_TOK + r1) * D_DIM;
        bool v0 = r0 < cnt, v1 = r1 < cnt;
#pragma unroll
        for (int fn = 0; fn < 4; fn++) {
            int c = n0 + wn * 32 + fn * 8 + 2 * tg;
            if (v0) *(float2*)(y0 + c) =
                make_float2(acc[fm][fn][0], acc[fm][fn][1]);
            if (v1) *(float2*)(y1 + c) =
                make_float2(acc[fm][fn][2], acc[fm][fn][3]);
        }
    }
}

// ---------------------------------------------------------------------------
// Combine -> d_out (single deterministic write per element)
// ---------------------------------------------------------------------------
__global__ void combine_kernel(const float* __restrict__ comb,
                               float* __restrict__ out)
{
    int idx = blockIdx.x * blockDim.x + threadIdx.x;
    if (idx >= T_TOK * D_DIM) return;
    int t = idx / D_DIM;
    int d = idx - t * D_DIM;
    float y  = 0.0f;
    int   np = g_np[t];
    for (int j = 0; j < np; j++) {
        int e = g_te[t * E_EXP + j];
        int s = g_ts[t * E_EXP + j];
        y += comb[t * E_EXP + e] * g_y[((size_t)e * T_TOK + s) * D_DIM + d];
    }
    out[idx] = y;
}

// ---------------------------------------------------------------------------
// Launch
// ---------------------------------------------------------------------------
extern "C" void kernel_launch(void* const* d_in, const int* in_sizes, int n_in,
                              void* d_out, int out_size)
{
    const float* tokens = (const float*)d_in[0];
    const float* disp   = (const float*)d_in[1];
    const float* comb   = (const float*)d_in[2];
    const float* Wg     = (const float*)d_in[3];
    const float* Wv     = (const float*)d_in[4];
    const float* Wo     = (const float*)d_in[5];
    const float* scale  = (const float*)d_in[6];
    float* out = (float*)d_out;

    static bool attr_set = false;
    if (!attr_set) {
        cudaFuncSetAttribute(gemm1_tc, cudaFuncAttributeMaxDynamicSharedMemorySize, SMEM1);
        cudaFuncSetAttribute(gemm2_tc, cudaFuncAttributeMaxDynamicSharedMemorySize, SMEM2);
        attr_set = true;
    }

    zero_counts_kernel<<<1, 32>>>();
    build_kernel<<<(T_TOK + 255) / 256, 256>>>(disp);

    __half* xh;  cudaGetSymbolAddress((void**)&xh,  g_xh);
    __half* wgh; cudaGetSymbolAddress((void**)&wgh, g_wgh);
    __half* wvh; cudaGetSymbolAddress((void**)&wvh, g_wvh);
    __half* woh; cudaGetSymbolAddress((void**)&woh, g_woh);

    {
        int ntot = X4 + 3 * W4;
        cvt_all_kernel<<<(ntot + 255) / 256, 256>>>(
            (const float4*)tokens, (const float4*)Wg, (const float4*)Wv,
            (const float4*)Wo, scale,
            (uint2*)xh, (uint2*)wgh, (uint2*)wvh, (uint2*)woh);
    }

    dim3 g1(T_TOK / 128, H_DIM / 128, E_EXP);   // (16, 24, 8)
    gemm1_tc<<<g1, 256, SMEM1>>>();

    dim3 g2(T_TOK / 128, D_DIM / 128, E_EXP);   // (16, 6, 8)
    gemm2_tc<<<g2, 256, SMEM2>>>();

    combine_kernel<<<(T_TOK * D_DIM + 255) / 256, 256>>>(comb, out);
}

// round 7
// speedup vs baseline: 5.5018x; 1.0148x over previous
#include <cuda_runtime.h>
#include <cuda_fp16.h>
#include <math.h>
#include <stdint.h>

// Problem constants (B=2, N=1024 -> T=2048 tokens; D=768; E=8; H=3072; K=2)
#define T_TOK 2048
#define D_DIM 768
#define E_EXP 8
#define H_DIM 3072

// ---------------------------------------------------------------------------
// Static device scratch (allocation-free per harness rules)
// ---------------------------------------------------------------------------
__device__ int    g_count[E_EXP];
__device__ int    g_tok[E_EXP * T_TOK];
__device__ int    g_np[T_TOK];
__device__ int    g_te[T_TOK * E_EXP];
__device__ int    g_ts[T_TOK * E_EXP];
__device__ __half g_hh[(size_t)E_EXP * T_TOK * H_DIM];    // gelu(gate)*value, fp16
__device__ float  g_y[(size_t)E_EXP * T_TOK * D_DIM];     // per-pair expert out
__device__ __half g_xh[(size_t)T_TOK * D_DIM];            // fp16 tokens
__device__ __half g_wgh[(size_t)E_EXP * H_DIM * D_DIM];   // fp16 Wg
__device__ __half g_wvh[(size_t)E_EXP * H_DIM * D_DIM];   // fp16 Wv
__device__ __half g_woh[(size_t)E_EXP * D_DIM * H_DIM];   // fp16 Wo * scale_e

// ---------------------------------------------------------------------------
// PTX helpers (family-generic: mma.sync sm80+, ldmatrix sm75+, cp.async sm80+)
// ---------------------------------------------------------------------------
#define MMA_F16(d, a, b)                                                         \
    asm volatile("mma.sync.aligned.m16n8k16.row.col.f32.f16.f16.f32 "            \
        "{%0,%1,%2,%3},{%4,%5,%6,%7},{%8,%9},{%0,%1,%2,%3};"                     \
        : "+f"((d)[0]), "+f"((d)[1]), "+f"((d)[2]), "+f"((d)[3])                  \
        : "r"((a)[0]), "r"((a)[1]), "r"((a)[2]), "r"((a)[3]),                     \
          "r"((b)[0]), "r"((b)[1]))

#define LDSM4(r, addr)                                                           \
    asm volatile("ldmatrix.sync.aligned.m8n8.x4.shared.b16 {%0,%1,%2,%3}, [%4];" \
        : "=r"((r)[0]), "=r"((r)[1]), "=r"((r)[2]), "=r"((r)[3]) : "r"(addr))

#define CP16(dst, src)                                                           \
    asm volatile("cp.async.cg.shared.global [%0], [%1], 16;"                     \
        :: "r"(dst), "l"(src))
#define CP16Z(dst, src, sz)                                                      \
    asm volatile("cp.async.cg.shared.global [%0], [%1], 16, %2;"                 \
        :: "r"(dst), "l"(src), "r"(sz))
#define CP_COMMIT() asm volatile("cp.async.commit_group;" ::: "memory")
#define CP_WAIT0()  asm volatile("cp.async.wait_group 0;" ::: "memory")
#define CP_WAIT1()  asm volatile("cp.async.wait_group 1;" ::: "memory")

__device__ __forceinline__ uint32_t sm_addr(const void* p) {
    return (uint32_t)__cvta_generic_to_shared(p);
}

// ---------------------------------------------------------------------------
// Routing build (verified R1)
// ---------------------------------------------------------------------------
__global__ void zero_counts_kernel() {
    int i = threadIdx.x;
    if (i < E_EXP) g_count[i] = 0;
}

__global__ void build_kernel(const float* __restrict__ disp) {
    int t = blockIdx.x * blockDim.x + threadIdx.x;
    if (t >= T_TOK) return;
    int np = 0;
#pragma unroll
    for (int e = 0; e < E_EXP; e++) {
        if (disp[t * E_EXP + e] > 0.0f) {
            int s = atomicAdd(&g_count[e], 1);
            g_tok[e * T_TOK + s] = t;
            g_te[t * E_EXP + np] = e;
            g_ts[t * E_EXP + np] = s;
            np++;
        }
    }
    g_np[t] = np;
}

// ---------------------------------------------------------------------------
// Fused fp32 -> fp16 conversion of all GEMM operands (single launch).
// ---------------------------------------------------------------------------
#define X4  (T_TOK * D_DIM / 4)            // 393216
#define W4  (E_EXP * H_DIM * D_DIM / 4)    // 4718592
#define EW4 (D_DIM * H_DIM / 4)            // 589824 (per-expert Wo float4s)

__global__ void cvt_all_kernel(const float4* __restrict__ tok,
                               const float4* __restrict__ wg,
                               const float4* __restrict__ wv,
                               const float4* __restrict__ wo,
                               const float*  __restrict__ scale,
                               uint2* __restrict__ xh, uint2* __restrict__ wgh,
                               uint2* __restrict__ wvh, uint2* __restrict__ woh)
{
    int i = blockIdx.x * blockDim.x + threadIdx.x;
    float4 f; uint2* dst; float sc = 1.0f;
    if (i < X4)                 { f = tok[i];              dst = xh  + i; }
    else {
        int j = i - X4;
        if (j < W4)             { f = wg[j];               dst = wgh + j; }
        else if (j < 2 * W4)    { j -= W4;  f = wv[j];     dst = wvh + j; }
        else if (j < 3 * W4)    { j -= 2 * W4;
                                  f = wo[j];               dst = woh + j;
                                  sc = scale[j / EW4]; }
        else return;
    }
    __half2 h01 = __floats2half2_rn(f.x * sc, f.y * sc);
    __half2 h23 = __floats2half2_rn(f.z * sc, f.w * sc);
    uint2 u;
    u.x = *(const uint32_t*)&h01;
    u.y = *(const uint32_t*)&h23;
    *dst = u;
}

// ---------------------------------------------------------------------------
// Tiling: block 128x128, 8 warps (2m x 4n), warp tile 64x32, KC = 64 halves.
// 3-stage cp.async ring; one __syncthreads per K-chunk.
// smem tile: 128 rows x pitch 72 halves (ldmatrix phases conflict-free).
// ---------------------------------------------------------------------------
#define KC     64
#define PH     72
#define MATB   (128 * PH * 2)       // 18432 B
#define BUF1B  (3 * MATB)           // X, G, V  (55296 B)
#define BUF2B  (2 * MATB)           // H, W     (36864 B)
#define STAGES 3
#define SMEM1  (STAGES * BUF1B)     // 165888 B
#define SMEM2  (STAGES * BUF2B)     // 110592 B

// ---------------------------------------------------------------------------
// Stage 1: gate = X@Wg^T, value = X@Wv^T (fp16 mma), fused GELU epilogue.
// ---------------------------------------------------------------------------
__global__ __launch_bounds__(256) void gemm1_tc()
{
    extern __shared__ __half smh[];
    const int e   = blockIdx.z;
    const int cnt = g_count[e];
    const int m0  = blockIdx.x * 128;
    if (m0 >= cnt) return;
    const int n0  = blockIdx.y * 128;

    const int tid  = threadIdx.x;
    const int lane = tid & 31;
    const int wid  = tid >> 5;
    const int wm   = wid >> 2;        // 0..1
    const int wn   = wid & 3;         // 0..3
    const int g    = lane >> 2;       // 0..7
    const int tg   = lane & 3;        // 0..3

    // ---- load duties: 12 cp.async (16B) per thread per 64-k chunk ----
    const int seg = tid & 7;
    const uint32_t sb = sm_addr(smh);
    const __half* xsrc[4]; uint32_t xsz[4]; uint32_t sdst[4];
    const __half* gsrc[4]; const __half* vsrc[4];
    const size_t ew = (size_t)e * H_DIM * D_DIM;
#pragma unroll
    for (int i = 0; i < 4; i++) {
        int r    = (tid >> 3) + 32 * i;      // 0..127
        int slot = m0 + r;
        bool v   = slot < cnt;
        int tok  = v ? g_tok[e * T_TOK + slot] : 0;
        xsrc[i]  = g_xh + (size_t)tok * D_DIM + seg * 8;
        xsz[i]   = v ? 16u : 0u;
        gsrc[i]  = g_wgh + ew + (size_t)(n0 + r) * D_DIM + seg * 8;
        vsrc[i]  = g_wvh + ew + (size_t)(n0 + r) * D_DIM + seg * 8;
        sdst[i]  = (uint32_t)(r * PH + seg * 8) * 2u;
    }

#define G1_LOAD(slot, k0) do {                                                   \
    uint32_t _b = sb + (uint32_t)(slot) * BUF1B;                                  \
    _Pragma("unroll")                                                             \
    for (int i = 0; i < 4; i++) {                                                 \
        CP16Z(_b + sdst[i],            (xsrc[i] + (k0)), xsz[i]);                 \
        CP16 (_b + MATB + sdst[i],     (gsrc[i] + (k0)));                         \
        CP16 (_b + 2 * MATB + sdst[i], (vsrc[i] + (k0)));                         \
    }                                                                             \
    CP_COMMIT();                                                                  \
} while (0)

    // ldmatrix lane bases (byte offsets into a tile)
    // A (x4): rows wm*64 + (lane&15), k-half (lane>>4)*8
    const uint32_t aoff = (uint32_t)((wm * 64 + (lane & 15)) * PH
                                     + ((lane >> 4) * 8)) * 2u;
    // B (x4 over fn pairs): rows wn*32 + (lane>>4)*8 + (lane&7),
    //                       k-half ((lane>>3)&1)*8
    const uint32_t boff = (uint32_t)((wn * 32 + ((lane >> 4) * 8) + (lane & 7)) * PH
                                     + (((lane >> 3) & 1) * 8)) * 2u;

    float accg[4][4][4] = {};
    float accv[4][4][4] = {};

    const int NIT = D_DIM / KC;   // 12
    G1_LOAD(0, 0);
    G1_LOAD(1, KC);

    int slot = 0;
#pragma unroll 1
    for (int it = 0; it < NIT; ++it) {
        if (it < NIT - 1) CP_WAIT1(); else CP_WAIT0();
        __syncthreads();

        if (it + 2 < NIT) {
            int ns = slot + 2; if (ns >= STAGES) ns -= STAGES;
            G1_LOAD(ns, (it + 2) * KC);
        }

        const uint32_t ba = sb + (uint32_t)slot * BUF1B;
        const uint32_t Xa = ba + aoff;
        const uint32_t Ga = ba + MATB + boff;
        const uint32_t Va = ba + 2 * MATB + boff;
#pragma unroll
        for (int ks = 0; ks < 4; ks++) {
            const uint32_t kb = ks * 32;           // 16 halves = 32 bytes
            uint32_t a[4][4];
#pragma unroll
            for (int fm = 0; fm < 4; fm++)
                LDSM4(a[fm], Xa + fm * (16 * PH * 2) + kb);
#pragma unroll
            for (int fp = 0; fp < 2; fp++) {       // fn pairs
                uint32_t bg[4], bv[4];
                LDSM4(bg, Ga + fp * (16 * PH * 2) + kb);
                LDSM4(bv, Va + fp * (16 * PH * 2) + kb);
#pragma unroll
                for (int fm = 0; fm < 4; fm++) {
                    MMA_F16(accg[fm][2 * fp],     a[fm], (bg + 0));
                    MMA_F16(accg[fm][2 * fp + 1], a[fm], (bg + 2));
                    MMA_F16(accv[fm][2 * fp],     a[fm], (bv + 0));
                    MMA_F16(accv[fm][2 * fp + 1], a[fm], (bv + 2));
                }
            }
        }
        slot++; if (slot >= STAGES) slot -= STAGES;
    }

    // ---- epilogue: h = gelu(gate) * value -> fp16 ----
#pragma unroll
    for (int fm = 0; fm < 4; fm++) {
        int r0 = m0 + wm * 64 + fm * 16 + g;
        int r1 = r0 + 8;
        __half* h0 = g_hh + ((size_t)e * T_TOK + r0) * H_DIM;
        __half* h1 = g_hh + ((size_t)e * T_TOK + r1) * H_DIM;
        bool v0 = r0 < cnt, v1 = r1 < cnt;
#pragma unroll
        for (int fn = 0; fn < 4; fn++) {
            int c = n0 + wn * 32 + fn * 8 + 2 * tg;
            if (v0) {
                float ga = accg[fm][fn][0], gb = accg[fm][fn][1];
                float oa = 0.5f * ga * (1.0f + erff(ga * 0.70710678118654752f))
                         * accv[fm][fn][0];
                float ob = 0.5f * gb * (1.0f + erff(gb * 0.70710678118654752f))
                         * accv[fm][fn][1];
                *(__half2*)(h0 + c) = __floats2half2_rn(oa, ob);
            }
            if (v1) {
                float ga = accg[fm][fn][2], gb = accg[fm][fn][3];
                float oa = 0.5f * ga * (1.0f + erff(ga * 0.70710678118654752f))
                         * accv[fm][fn][2];
                float ob = 0.5f * gb * (1.0f + erff(gb * 0.70710678118654752f))
                         * accv[fm][fn][3];
                *(__half2*)(h1 + c) = __floats2half2_rn(oa, ob);
            }
        }
    }
}

// ---------------------------------------------------------------------------
// Stage 2: y = h @ (Wo*scale)^T. Block 128 x 128, K = 3072.
// ---------------------------------------------------------------------------
__global__ __launch_bounds__(256) void gemm2_tc()
{
    extern __shared__ __half smh[];
    const int e   = blockIdx.z;
    const int cnt = g_count[e];
    const int m0  = blockIdx.x * 128;
    if (m0 >= cnt) return;
    const int n0  = blockIdx.y * 128;

    const int tid  = threadIdx.x;
    const int lane = tid & 31;
    const int wid  = tid >> 5;
    const int wm   = wid >> 2;
    const int wn   = wid & 3;
    const int g    = lane >> 2;
    const int tg   = lane & 3;

    const int seg = tid & 7;
    const uint32_t sb = sm_addr(smh);
    const __half* asrc[4]; uint32_t asz[4]; const __half* bsrc[4]; uint32_t sdst[4];
    const size_t ewo = (size_t)e * D_DIM * H_DIM;
#pragma unroll
    for (int i = 0; i < 4; i++) {
        int r    = (tid >> 3) + 32 * i;
        int slot = m0 + r;
        bool v   = slot < cnt;
        asrc[i]  = g_hh + ((size_t)e * T_TOK + (v ? slot : 0)) * H_DIM + seg * 8;
        asz[i]   = v ? 16u : 0u;
        bsrc[i]  = g_woh + ewo + (size_t)(n0 + r) * H_DIM + seg * 8;
        sdst[i]  = (uint32_t)(r * PH + seg * 8) * 2u;
    }

#define G2_LOAD(slot, k0) do {                                                   \
    uint32_t _b = sb + (uint32_t)(slot) * BUF2B;                                  \
    _Pragma("unroll")                                                             \
    for (int i = 0; i < 4; i++) {                                                 \
        CP16Z(_b + sdst[i],        (asrc[i] + (k0)), asz[i]);                     \
        CP16 (_b + MATB + sdst[i], (bsrc[i] + (k0)));                             \
    }                                                                             \
    CP_COMMIT();                                                                  \
} while (0)

    const uint32_t aoff = (uint32_t)((wm * 64 + (lane & 15)) * PH
                                     + ((lane >> 4) * 8)) * 2u;
    const uint32_t boff = (uint32_t)((wn * 32 + ((lane >> 4) * 8) + (lane & 7)) * PH
                                     + (((lane >> 3) & 1) * 8)) * 2u;

    float acc[4][4][4] = {};

    const int NIT = H_DIM / KC;   // 48
    G2_LOAD(0, 0);
    G2_LOAD(1, KC);

    int slot = 0;
#pragma unroll 1
    for (int it = 0; it < NIT; ++it) {
        if (it < NIT - 1) CP_WAIT1(); else CP_WAIT0();
        __syncthreads();

        if (it + 2 < NIT) {
            int ns = slot + 2; if (ns >= STAGES) ns -= STAGES;
            G2_LOAD(ns, (it + 2) * KC);
        }

        const uint32_t ba = sb + (uint32_t)slot * BUF2B;
        const uint32_t Aa = ba + aoff;
        const uint32_t Ba = ba + MATB + boff;
#pragma unroll
        for (int ks = 0; ks < 4; ks++) {
            const uint32_t kb = ks * 32;
            uint32_t a[4][4];
#pragma unroll
            for (int fm = 0; fm < 4; fm++)
                LDSM4(a[fm], Aa + fm * (16 * PH * 2) + kb);
#pragma unroll
            for (int fp = 0; fp < 2; fp++) {
                uint32_t b[4];
                LDSM4(b, Ba + fp * (16 * PH * 2) + kb);
#pragma unroll
                for (int fm = 0; fm < 4; fm++) {
                    MMA_F16(acc[fm][2 * fp],     a[fm], (b + 0));
                    MMA_F16(acc[fm][2 * fp + 1], a[fm], (b + 2));
                }
            }
        }
        slot++; if (slot >= STAGES) slot -= STAGES;
    }

#pragma unroll
    for (int fm = 0; fm < 4; fm++) {
        int r0 = m0 + wm * 64 + fm * 16 + g;
        int r1 = r0 + 8;
        float* y0 = g_y + ((size_t)e * T_TOK + r0) * D_DIM;
        float* y1 = g_y + ((size_t)e * T_TOK + r1) * D_DIM;
        bool v0 = r0 < cnt, v1 = r1 < cnt;
#pragma unroll
        for (int fn = 0; fn < 4; fn++) {
            int c = n0 + wn * 32 + fn * 8 + 2 * tg;
            if (v0) *(float2*)(y0 + c) =
                make_float2(acc[fm][fn][0], acc[fm][fn][1]);
            if (v1) *(float2*)(y1 + c) =
                make_float2(acc[fm][fn][2], acc[fm][fn][3]);
        }
    }
}

// ---------------------------------------------------------------------------
// Combine -> d_out (single deterministic write per element)
// ---------------------------------------------------------------------------
__global__ void combine_kernel(const float* __restrict__ comb,
                               float* __restrict__ out)
{
    int idx = blockIdx.x * blockDim.x + threadIdx.x;
    if (idx >= T_TOK * D_DIM) return;
    int t = idx / D_DIM;
    int d = idx - t * D_DIM;
    float y  = 0.0f;
    int   np = g_np[t];
    for (int j = 0; j < np; j++) {
        int e = g_te[t * E_EXP + j];
        int s = g_ts[t * E_EXP + j];
        y += comb[t * E_EXP + e] * g_y[((size_t)e * T_TOK + s) * D_DIM + d];
    }
    out[idx] = y;
}

// ---------------------------------------------------------------------------
// Launch
// ---------------------------------------------------------------------------
extern "C" void kernel_launch(void* const* d_in, const int* in_sizes, int n_in,
                              void* d_out, int out_size)
{
    const float* tokens = (const float*)d_in[0];
    const float* disp   = (const float*)d_in[1];
    const float* comb   = (const float*)d_in[2];
    const float* Wg     = (const float*)d_in[3];
    const float* Wv     = (const float*)d_in[4];
    const float* Wo     = (const float*)d_in[5];
    const float* scale  = (const float*)d_in[6];
    float* out = (float*)d_out;

    static bool attr_set = false;
    if (!attr_set) {
        cudaFuncSetAttribute(gemm1_tc, cudaFuncAttributeMaxDynamicSharedMemorySize, SMEM1);
        cudaFuncSetAttribute(gemm2_tc, cudaFuncAttributeMaxDynamicSharedMemorySize, SMEM2);
        attr_set = true;
    }

    zero_counts_kernel<<<1, 32>>>();
    build_kernel<<<(T_TOK + 255) / 256, 256>>>(disp);

    __half* xh;  cudaGetSymbolAddress((void**)&xh,  g_xh);
    __half* wgh; cudaGetSymbolAddress((void**)&wgh, g_wgh);
    __half* wvh; cudaGetSymbolAddress((void**)&wvh, g_wvh);
    __half* woh; cudaGetSymbolAddress((void**)&woh, g_woh);

    {
        int ntot = X4 + 3 * W4;
        cvt_all_kernel<<<(ntot + 255) / 256, 256>>>(
            (const float4*)tokens, (const float4*)Wg, (const float4*)Wv,
            (const float4*)Wo, scale,
            (uint2*)xh, (uint2*)wgh, (uint2*)wvh, (uint2*)woh);
    }

    dim3 g1(T_TOK / 128, H_DIM / 128, E_EXP);   // (16, 24, 8)
    gemm1_tc<<<g1, 256, SMEM1>>>();

    dim3 g2(T_TOK / 128, D_DIM / 128, E_EXP);   // (16, 6, 8)
    gemm2_tc<<<g2, 256, SMEM2>>>();

    combine_kernel<<<(T_TOK * D_DIM + 255) / 256, 256>>>(comb, out);
}

// round 8
// speedup vs baseline: 5.6752x; 1.0315x over previous
#include <cuda_runtime.h>
#include <cuda_fp16.h>
#include <math.h>
#include <stdint.h>

// Problem constants (B=2, N=1024 -> T=2048 tokens; D=768; E=8; H=3072; K=2)
#define T_TOK 2048
#define D_DIM 768
#define E_EXP 8
#define H_DIM 3072

// ---------------------------------------------------------------------------
// Static device scratch (allocation-free per harness rules)
// ---------------------------------------------------------------------------
__device__ int    g_count[E_EXP];
__device__ int    g_tok[E_EXP * T_TOK];
__device__ int    g_np[T_TOK];
__device__ int    g_te[T_TOK * E_EXP];
__device__ int    g_ts[T_TOK * E_EXP];
__device__ __half g_hh[(size_t)E_EXP * T_TOK * H_DIM];    // gelu(gate)*value, fp16
__device__ float  g_y[(size_t)E_EXP * T_TOK * D_DIM];     // expert out, K-half 0
__device__ float  g_y2[(size_t)E_EXP * T_TOK * D_DIM];    // expert out, K-half 1
__device__ __half g_xh[(size_t)T_TOK * D_DIM];            // fp16 tokens
__device__ __half g_wgh[(size_t)E_EXP * H_DIM * D_DIM];   // fp16 Wg
__device__ __half g_wvh[(size_t)E_EXP * H_DIM * D_DIM];   // fp16 Wv
__device__ __half g_woh[(size_t)E_EXP * D_DIM * H_DIM];   // fp16 Wo * scale_e

// ---------------------------------------------------------------------------
// PTX helpers (family-generic: mma.sync sm80+, ldmatrix sm75+, cp.async sm80+)
// ---------------------------------------------------------------------------
#define MMA_F16(d, a, b)                                                         \
    asm volatile("mma.sync.aligned.m16n8k16.row.col.f32.f16.f16.f32 "            \
        "{%0,%1,%2,%3},{%4,%5,%6,%7},{%8,%9},{%0,%1,%2,%3};"                     \
        : "+f"((d)[0]), "+f"((d)[1]), "+f"((d)[2]), "+f"((d)[3])                  \
        : "r"((a)[0]), "r"((a)[1]), "r"((a)[2]), "r"((a)[3]),                     \
          "r"((b)[0]), "r"((b)[1]))

#define LDSM4(r, addr)                                                           \
    asm volatile("ldmatrix.sync.aligned.m8n8.x4.shared.b16 {%0,%1,%2,%3}, [%4];" \
        : "=r"((r)[0]), "=r"((r)[1]), "=r"((r)[2]), "=r"((r)[3]) : "r"(addr))

#define CP16(dst, src)                                                           \
    asm volatile("cp.async.cg.shared.global [%0], [%1], 16;"                     \
        :: "r"(dst), "l"(src))
#define CP16Z(dst, src, sz)                                                      \
    asm volatile("cp.async.cg.shared.global [%0], [%1], 16, %2;"                 \
        :: "r"(dst), "l"(src), "r"(sz))
#define CP_COMMIT() asm volatile("cp.async.commit_group;" ::: "memory")
#define CP_WAIT0()  asm volatile("cp.async.wait_group 0;" ::: "memory")
#define CP_WAIT1()  asm volatile("cp.async.wait_group 1;" ::: "memory")

__device__ __forceinline__ uint32_t sm_addr(const void* p) {
    return (uint32_t)__cvta_generic_to_shared(p);
}

// ---------------------------------------------------------------------------
// Routing build (verified R1)
// ---------------------------------------------------------------------------
__global__ void zero_counts_kernel() {
    int i = threadIdx.x;
    if (i < E_EXP) g_count[i] = 0;
}

__global__ void build_kernel(const float* __restrict__ disp) {
    int t = blockIdx.x * blockDim.x + threadIdx.x;
    if (t >= T_TOK) return;
    int np = 0;
#pragma unroll
    for (int e = 0; e < E_EXP; e++) {
        if (disp[t * E_EXP + e] > 0.0f) {
            int s = atomicAdd(&g_count[e], 1);
            g_tok[e * T_TOK + s] = t;
            g_te[t * E_EXP + np] = e;
            g_ts[t * E_EXP + np] = s;
            np++;
        }
    }
    g_np[t] = np;
}

// ---------------------------------------------------------------------------
// Fused fp32 -> fp16 conversion of all GEMM operands (single launch).
// ---------------------------------------------------------------------------
#define X4  (T_TOK * D_DIM / 4)            // 393216
#define W4  (E_EXP * H_DIM * D_DIM / 4)    // 4718592
#define EW4 (D_DIM * H_DIM / 4)            // 589824 (per-expert Wo float4s)

__global__ void cvt_all_kernel(const float4* __restrict__ tok,
                               const float4* __restrict__ wg,
                               const float4* __restrict__ wv,
                               const float4* __restrict__ wo,
                               const float*  __restrict__ scale,
                               uint2* __restrict__ xh, uint2* __restrict__ wgh,
                               uint2* __restrict__ wvh, uint2* __restrict__ woh)
{
    int i = blockIdx.x * blockDim.x + threadIdx.x;
    float4 f; uint2* dst; float sc = 1.0f;
    if (i < X4)                 { f = tok[i];              dst = xh  + i; }
    else {
        int j = i - X4;
        if (j < W4)             { f = wg[j];               dst = wgh + j; }
        else if (j < 2 * W4)    { j -= W4;  f = wv[j];     dst = wvh + j; }
        else if (j < 3 * W4)    { j -= 2 * W4;
                                  f = wo[j];               dst = woh + j;
                                  sc = scale[j / EW4]; }
        else return;
    }
    __half2 h01 = __floats2half2_rn(f.x * sc, f.y * sc);
    __half2 h23 = __floats2half2_rn(f.z * sc, f.w * sc);
    uint2 u;
    u.x = *(const uint32_t*)&h01;
    u.y = *(const uint32_t*)&h23;
    *dst = u;
}

// ---------------------------------------------------------------------------
// Tiling: block 128x128, 16 warps (4m x 4n), warp tile 32x32, KC = 64 halves.
// 3-stage cp.async ring; one __syncthreads per K-chunk.
// ---------------------------------------------------------------------------
#define KC     64
#define PH     72
#define MATB   (128 * PH * 2)       // 18432 B
#define BUF1B  (3 * MATB)           // X, G, V  (55296 B)
#define BUF2B  (2 * MATB)           // H, W     (36864 B)
#define STAGES 3
#define SMEM1  (STAGES * BUF1B)     // 165888 B
#define SMEM2  (STAGES * BUF2B)     // 110592 B

// ---------------------------------------------------------------------------
// Stage 1: gate = X@Wg^T, value = X@Wv^T (fp16 mma), fused GELU epilogue.
// 512 threads; warp (wm,wn) covers rows wm*32..+31, cols wn*32..+31.
// ---------------------------------------------------------------------------
__global__ __launch_bounds__(512, 1) void gemm1_tc()
{
    extern __shared__ __half smh[];
    const int e   = blockIdx.z;
    const int cnt = g_count[e];
    const int m0  = blockIdx.x * 128;
    if (m0 >= cnt) return;
    const int n0  = blockIdx.y * 128;

    const int tid  = threadIdx.x;
    const int lane = tid & 31;
    const int wid  = tid >> 5;
    const int wm   = wid >> 2;        // 0..3
    const int wn   = wid & 3;         // 0..3
    const int g    = lane >> 2;       // 0..7
    const int tg   = lane & 3;        // 0..3

    // ---- load duties: 6 cp.async (16B) per thread per 64-k chunk ----
    const int seg = tid & 7;
    const uint32_t sb = sm_addr(smh);
    const __half* xsrc[2]; uint32_t xsz[2]; uint32_t sdst[2];
    const __half* gsrc[2]; const __half* vsrc[2];
    const size_t ew = (size_t)e * H_DIM * D_DIM;
#pragma unroll
    for (int i = 0; i < 2; i++) {
        int r    = (tid >> 3) + 64 * i;      // 0..127
        int slot = m0 + r;
        bool v   = slot < cnt;
        int tok  = v ? g_tok[e * T_TOK + slot] : 0;
        xsrc[i]  = g_xh + (size_t)tok * D_DIM + seg * 8;
        xsz[i]   = v ? 16u : 0u;
        gsrc[i]  = g_wgh + ew + (size_t)(n0 + r) * D_DIM + seg * 8;
        vsrc[i]  = g_wvh + ew + (size_t)(n0 + r) * D_DIM + seg * 8;
        sdst[i]  = (uint32_t)(r * PH + seg * 8) * 2u;
    }

#define G1_LOAD(slot, k0) do {                                                   \
    uint32_t _b = sb + (uint32_t)(slot) * BUF1B;                                  \
    _Pragma("unroll")                                                             \
    for (int i = 0; i < 2; i++) {                                                 \
        CP16Z(_b + sdst[i],            (xsrc[i] + (k0)), xsz[i]);                 \
        CP16 (_b + MATB + sdst[i],     (gsrc[i] + (k0)));                         \
        CP16 (_b + 2 * MATB + sdst[i], (vsrc[i] + (k0)));                         \
    }                                                                             \
    CP_COMMIT();                                                                  \
} while (0)

    // A (x4): rows wm*32 + (lane&15), k-half (lane>>4)*8
    const uint32_t aoff = (uint32_t)((wm * 32 + (lane & 15)) * PH
                                     + ((lane >> 4) * 8)) * 2u;
    // B (x4 over fn pairs): rows wn*32 + (lane>>4)*8 + (lane&7),
    //                       k-half ((lane>>3)&1)*8
    const uint32_t boff = (uint32_t)((wn * 32 + ((lane >> 4) * 8) + (lane & 7)) * PH
                                     + (((lane >> 3) & 1) * 8)) * 2u;

    float accg[2][4][4] = {};
    float accv[2][4][4] = {};

    const int NIT = D_DIM / KC;   // 12
    G1_LOAD(0, 0);
    G1_LOAD(1, KC);

    int slot = 0;
#pragma unroll 1
    for (int it = 0; it < NIT; ++it) {
        if (it < NIT - 1) CP_WAIT1(); else CP_WAIT0();
        __syncthreads();

        if (it + 2 < NIT) {
            int ns = slot + 2; if (ns >= STAGES) ns -= STAGES;
            G1_LOAD(ns, (it + 2) * KC);
        }

        const uint32_t ba = sb + (uint32_t)slot * BUF1B;
        const uint32_t Xa = ba + aoff;
        const uint32_t Ga = ba + MATB + boff;
        const uint32_t Va = ba + 2 * MATB + boff;
#pragma unroll
        for (int ks = 0; ks < 4; ks++) {
            const uint32_t kb = ks * 32;           // 16 halves = 32 bytes
            uint32_t a[2][4];
#pragma unroll
            for (int fm = 0; fm < 2; fm++)
                LDSM4(a[fm], Xa + fm * (16 * PH * 2) + kb);
#pragma unroll
            for (int fp = 0; fp < 2; fp++) {       // fn pairs
                uint32_t bg[4], bv[4];
                LDSM4(bg, Ga + fp * (16 * PH * 2) + kb);
                LDSM4(bv, Va + fp * (16 * PH * 2) + kb);
#pragma unroll
                for (int fm = 0; fm < 2; fm++) {
                    MMA_F16(accg[fm][2 * fp],     a[fm], (bg + 0));
                    MMA_F16(accg[fm][2 * fp + 1], a[fm], (bg + 2));
                    MMA_F16(accv[fm][2 * fp],     a[fm], (bv + 0));
                    MMA_F16(accv[fm][2 * fp + 1], a[fm], (bv + 2));
                }
            }
        }
        slot++; if (slot >= STAGES) slot -= STAGES;
    }

    // ---- epilogue: h = gelu(gate) * value -> fp16 ----
#pragma unroll
    for (int fm = 0; fm < 2; fm++) {
        int r0 = m0 + wm * 32 + fm * 16 + g;
        int r1 = r0 + 8;
        __half* h0 = g_hh + ((size_t)e * T_TOK + r0) * H_DIM;
        __half* h1 = g_hh + ((size_t)e * T_TOK + r1) * H_DIM;
        bool v0 = r0 < cnt, v1 = r1 < cnt;
#pragma unroll
        for (int fn = 0; fn < 4; fn++) {
            int c = n0 + wn * 32 + fn * 8 + 2 * tg;
            if (v0) {
                float ga = accg[fm][fn][0], gb = accg[fm][fn][1];
                float oa = 0.5f * ga * (1.0f + erff(ga * 0.70710678118654752f))
                         * accv[fm][fn][0];
                float ob = 0.5f * gb * (1.0f + erff(gb * 0.70710678118654752f))
                         * accv[fm][fn][1];
                *(__half2*)(h0 + c) = __floats2half2_rn(oa, ob);
            }
            if (v1) {
                float ga = accg[fm][fn][2], gb = accg[fm][fn][3];
                float oa = 0.5f * ga * (1.0f + erff(ga * 0.70710678118654752f))
                         * accv[fm][fn][2];
                float ob = 0.5f * gb * (1.0f + erff(gb * 0.70710678118654752f))
                         * accv[fm][fn][3];
                *(__half2*)(h1 + c) = __floats2half2_rn(oa, ob);
            }
        }
    }
}

// ---------------------------------------------------------------------------
// Stage 2: y = h @ (Wo*scale)^T, split-K x2 (deterministic: separate buffers).
// blockIdx.z = e*2 + khalf. K-half range: [khalf*1536, +1536).
// ---------------------------------------------------------------------------
__global__ __launch_bounds__(512, 1) void gemm2_tc()
{
    extern __shared__ __half smh[];
    const int e     = blockIdx.z >> 1;
    const int kh    = blockIdx.z & 1;
    const int cnt   = g_count[e];
    const int m0    = blockIdx.x * 128;
    if (m0 >= cnt) return;
    const int n0    = blockIdx.y * 128;
    const int kbase = kh * (H_DIM / 2);

    const int tid  = threadIdx.x;
    const int lane = tid & 31;
    const int wid  = tid >> 5;
    const int wm   = wid >> 2;
    const int wn   = wid & 3;
    const int g    = lane >> 2;
    const int tg   = lane & 3;

    const int seg = tid & 7;
    const uint32_t sb = sm_addr(smh);
    const __half* asrc[2]; uint32_t asz[2]; const __half* bsrc[2]; uint32_t sdst[2];
    const size_t ewo = (size_t)e * D_DIM * H_DIM;
#pragma unroll
    for (int i = 0; i < 2; i++) {
        int r    = (tid >> 3) + 64 * i;
        int slot = m0 + r;
        bool v   = slot < cnt;
        asrc[i]  = g_hh + ((size_t)e * T_TOK + (v ? slot : 0)) * H_DIM
                 + kbase + seg * 8;
        asz[i]   = v ? 16u : 0u;
        bsrc[i]  = g_woh + ewo + (size_t)(n0 + r) * H_DIM + kbase + seg * 8;
        sdst[i]  = (uint32_t)(r * PH + seg * 8) * 2u;
    }

#define G2_LOAD(slot, k0) do {                                                   \
    uint32_t _b = sb + (uint32_t)(slot) * BUF2B;                                  \
    _Pragma("unroll")                                                             \
    for (int i = 0; i < 2; i++) {                                                 \
        CP16Z(_b + sdst[i],        (asrc[i] + (k0)), asz[i]);                     \
        CP16 (_b + MATB + sdst[i], (bsrc[i] + (k0)));                             \
    }                                                                             \
    CP_COMMIT();                                                                  \
} while (0)

    const uint32_t aoff = (uint32_t)((wm * 32 + (lane & 15)) * PH
                                     + ((lane >> 4) * 8)) * 2u;
    const uint32_t boff = (uint32_t)((wn * 32 + ((lane >> 4) * 8) + (lane & 7)) * PH
                                     + (((lane >> 3) & 1) * 8)) * 2u;

    float acc[2][4][4] = {};

    const int NIT = (H_DIM / 2) / KC;   // 24
    G2_LOAD(0, 0);
    G2_LOAD(1, KC);

    int slot = 0;
#pragma unroll 1
    for (int it = 0; it < NIT; ++it) {
        if (it < NIT - 1) CP_WAIT1(); else CP_WAIT0();
        __syncthreads();

        if (it + 2 < NIT) {
            int ns = slot + 2; if (ns >= STAGES) ns -= STAGES;
            G2_LOAD(ns, (it + 2) * KC);
        }

        const uint32_t ba = sb + (uint32_t)slot * BUF2B;
        const uint32_t Aa = ba + aoff;
        const uint32_t Ba = ba + MATB + boff;
#pragma unroll
        for (int ks = 0; ks < 4; ks++) {
            const uint32_t kb = ks * 32;
            uint32_t a[2][4];
#pragma unroll
            for (int fm = 0; fm < 2; fm++)
                LDSM4(a[fm], Aa + fm * (16 * PH * 2) + kb);
#pragma unroll
            for (int fp = 0; fp < 2; fp++) {
                uint32_t b[4];
                LDSM4(b, Ba + fp * (16 * PH * 2) + kb);
#pragma unroll
                for (int fm = 0; fm < 2; fm++) {
                    MMA_F16(acc[fm][2 * fp],     a[fm], (b + 0));
                    MMA_F16(acc[fm][2 * fp + 1], a[fm], (b + 2));
                }
            }
        }
        slot++; if (slot >= STAGES) slot -= STAGES;
    }

    float* ybuf = kh ? g_y2 : g_y;
#pragma unroll
    for (int fm = 0; fm < 2; fm++) {
        int r0 = m0 + wm * 32 + fm * 16 + g;
        int r1 = r0 + 8;
        float* y0 = ybuf + ((size_t)e * T_TOK + r0) * D_DIM;
        float* y1 = ybuf + ((size_t)e * T_TOK + r1) * D_DIM;
        bool v0 = r0 < cnt, v1 = r1 < cnt;
#pragma unroll
        for (int fn = 0; fn < 4; fn++) {
            int c = n0 + wn * 32 + fn * 8 + 2 * tg;
            if (v0) *(float2*)(y0 + c) =
                make_float2(acc[fm][fn][0], acc[fm][fn][1]);
            if (v1) *(float2*)(y1 + c) =
                make_float2(acc[fm][fn][2], acc[fm][fn][3]);
        }
    }
}

// ---------------------------------------------------------------------------
// Combine -> d_out (single deterministic write per element; sums K-halves)
// ---------------------------------------------------------------------------
__global__ void combine_kernel(const float* __restrict__ comb,
                               float* __restrict__ out)
{
    int idx = blockIdx.x * blockDim.x + threadIdx.x;
    if (idx >= T_TOK * D_DIM) return;
    int t = idx / D_DIM;
    int d = idx - t * D_DIM;
    float y  = 0.0f;
    int   np = g_np[t];
    for (int j = 0; j < np; j++) {
        int e = g_te[t * E_EXP + j];
        int s = g_ts[t * E_EXP + j];
        size_t o = ((size_t)e * T_TOK + s) * D_DIM + d;
        y += comb[t * E_EXP + e] * (g_y[o] + g_y2[o]);
    }
    out[idx] = y;
}

// ---------------------------------------------------------------------------
// Launch
// ---------------------------------------------------------------------------
extern "C" void kernel_launch(void* const* d_in, const int* in_sizes, int n_in,
                              void* d_out, int out_size)
{
    const float* tokens = (const float*)d_in[0];
    const float* disp   = (const float*)d_in[1];
    const float* comb   = (const float*)d_in[2];
    const float* Wg     = (const float*)d_in[3];
    const float* Wv     = (const float*)d_in[4];
    const float* Wo     = (const float*)d_in[5];
    const float* scale  = (const float*)d_in[6];
    float* out = (float*)d_out;

    static bool attr_set = false;
    if (!attr_set) {
        cudaFuncSetAttribute(gemm1_tc, cudaFuncAttributeMaxDynamicSharedMemorySize, SMEM1);
        cudaFuncSetAttribute(gemm2_tc, cudaFuncAttributeMaxDynamicSharedMemorySize, SMEM2);
        attr_set = true;
    }

    zero_counts_kernel<<<1, 32>>>();
    build_kernel<<<(T_TOK + 255) / 256, 256>>>(disp);

    __half* xh;  cudaGetSymbolAddress((void**)&xh,  g_xh);
    __half* wgh; cudaGetSymbolAddress((void**)&wgh, g_wgh);
    __half* wvh; cudaGetSymbolAddress((void**)&wvh, g_wvh);
    __half* woh; cudaGetSymbolAddress((void**)&woh, g_woh);

    {
        int ntot = X4 + 3 * W4;
        cvt_all_kernel<<<(ntot + 255) / 256, 256>>>(
            (const float4*)tokens, (const float4*)Wg, (const float4*)Wv,
            (const float4*)Wo, scale,
            (uint2*)xh, (uint2*)wgh, (uint2*)wvh, (uint2*)woh);
    }

    dim3 g1(T_TOK / 128, H_DIM / 128, E_EXP);       // (16, 24, 8)
    gemm1_tc<<<g1, 512, SMEM1>>>();

    dim3 g2(T_TOK / 128, D_DIM / 128, 2 * E_EXP);   // (16, 6, 16) split-K
    gemm2_tc<<<g2, 512, SMEM2>>>();

    combine_kernel<<<(T_TOK * D_DIM + 255) / 256, 256>>>(comb, out);
}